// round 4
// baseline (speedup 1.0000x reference)
#include <cuda_runtime.h>
#include <stdint.h>

// Problem constants
constexpr int Bv = 16;
constexpr int Hv = 4;
constexpr int Dv = 64;     // head dim
constexpr int Cv = 256;    // channels = Hv*Dv
constexpr int Nv = 1024;   // sequence length (32*32)

// ---------------- static device scratch (no allocations allowed) -----------
__device__ float g_Q[(size_t)Bv * Cv * Nv];                 // [bh][d][n]
__device__ float g_K[(size_t)Bv * Cv * Nv];
__device__ float g_V[(size_t)Bv * Cv * Nv];
__device__ float g_L[(size_t)Bv * Hv * Nv * Nv];            // logits / probs

// ---------------- small helpers --------------------------------------------
__device__ __forceinline__ float tf32_rna(float x) {
    uint32_t u;
    asm("cvt.rna.tf32.f32 %0, %1;" : "=r"(u) : "f"(x));
    return __uint_as_float(u);
}
__device__ __forceinline__ void tf32_split(float x, float& hi, float& lo) {
    hi = tf32_rna(x);
    lo = tf32_rna(x - hi);
}
// D += A(16x8,row) * B(8x8,col)   tf32
__device__ __forceinline__ void mma8(float acc[4],
                                     float a0, float a1, float a2, float a3,
                                     float b0, float b1) {
    asm volatile(
        "mma.sync.aligned.m16n8k8.row.col.f32.tf32.tf32.f32 "
        "{%0,%1,%2,%3},{%4,%5,%6,%7},{%8,%9},{%0,%1,%2,%3};\n"
        : "+f"(acc[0]), "+f"(acc[1]), "+f"(acc[2]), "+f"(acc[3])
        : "r"(__float_as_uint(a0)), "r"(__float_as_uint(a1)),
          "r"(__float_as_uint(a2)), "r"(__float_as_uint(a3)),
          "r"(__float_as_uint(b0)), "r"(__float_as_uint(b1)));
}

// ---------------------------------------------------------------------------
// Kernel 1: QKV projection (fp32 SIMT, exact). Y = Wcat(768x256) @ x_b + bias.
// ---------------------------------------------------------------------------
__global__ void proj_kernel(const float* __restrict__ x,
                            const float* __restrict__ Wq, const float* __restrict__ bq,
                            const float* __restrict__ Wk, const float* __restrict__ bk,
                            const float* __restrict__ Wv, const float* __restrict__ bv) {
    const int b  = blockIdx.z;
    const int o0 = blockIdx.y * 64;
    const int n0 = blockIdx.x * 64;
    const int tid = threadIdx.x;
    const int tx = tid & 15, ty = tid >> 4;

    const int which = o0 >> 8;
    const float* W    = (which == 0) ? Wq : (which == 1) ? Wk : Wv;
    const float* bias = (which == 0) ? bq : (which == 1) ? bk : bv;
    float* dst        = (which == 0) ? g_Q : (which == 1) ? g_K : g_V;
    const int or0 = o0 & 255;

    __shared__ float As[16][65];
    __shared__ float Bs[16][64];

    const float* xb = x + (size_t)b * Cv * Nv;

    float acc[4][4] = {};
    for (int k0 = 0; k0 < Cv; k0 += 16) {
        {
            int oo = tid >> 4, kk = tid & 15;
            #pragma unroll
            for (int r = 0; r < 4; r++)
                As[kk][oo + r * 16] = W[(size_t)(or0 + oo + r * 16) * Cv + k0 + kk];
        }
        {
            int nn = tid & 63, kk4 = tid >> 6;
            #pragma unroll
            for (int r = 0; r < 4; r++)
                Bs[kk4 + r * 4][nn] = xb[(size_t)(k0 + kk4 + r * 4) * Nv + n0 + nn];
        }
        __syncthreads();
        #pragma unroll
        for (int kk = 0; kk < 16; kk++) {
            float a[4], bb[4];
            #pragma unroll
            for (int i = 0; i < 4; i++) a[i] = As[kk][ty * 4 + i];
            #pragma unroll
            for (int j = 0; j < 4; j++) bb[j] = Bs[kk][tx * 4 + j];
            #pragma unroll
            for (int i = 0; i < 4; i++)
                #pragma unroll
                for (int j = 0; j < 4; j++)
                    acc[i][j] += a[i] * bb[j];
        }
        __syncthreads();
    }
    #pragma unroll
    for (int i = 0; i < 4; i++) {
        int orow = or0 + ty * 4 + i;
        float bval = bias[orow];
        float* drow = dst + ((size_t)b * Cv + orow) * Nv + n0 + tx * 4;
        #pragma unroll
        for (int j = 0; j < 4; j++) drow[j] = acc[i][j] + bval;
    }
}

// ---------------------------------------------------------------------------
// Kernel 2: logits via tensor cores (3xTF32 split => fp32-accurate).
// S[i][j] = sum_{dd=0..127} A[dd][i] * B[dd][j], A=[Q;R], B=[K;Q].
// CTA: 128x128 tile, 8 warps (warp tile 32x64), k-tile 16.
// ---------------------------------------------------------------------------
constexpr int SA = 136;   // smem row stride (floats): bank = (8k+i)&31 -> conflict-free
__global__ void __launch_bounds__(256, 2)
logits_mma_kernel(const float* __restrict__ relh, const float* __restrict__ relw) {
    const int bh = blockIdx.z;
    const int h  = bh & 3;
    const int i0 = blockIdx.y * 128;
    const int j0 = blockIdx.x * 128;
    const int tid = threadIdx.x;
    const int warp = tid >> 5, lane = tid & 31;
    const int g = lane >> 2, tig = lane & 3;
    const int wi = (warp >> 1) * 32;     // warp i-offset (4 rows of warps)
    const int wj = (warp & 1) * 64;      // warp j-offset (2 cols of warps)

    const float* Qbh = g_Q + (size_t)bh * Dv * Nv;
    const float* Kbh = g_K + (size_t)bh * Dv * Nv;
    float* Lbh = g_L + (size_t)bh * Nv * Nv;

    __shared__ float AsHi[16 * SA], AsLo[16 * SA];
    __shared__ float BsHi[16 * SA], BsLo[16 * SA];

    float acc[2][8][4] = {};

    for (int k0 = 0; k0 < 2 * Dv; k0 += 16) {
        // ---- stage: 16 x 128 fp32 tiles -> tf32 hi/lo in smem ----
        #pragma unroll
        for (int r = 0; r < 2; r++) {
            int t4 = tid + r * 256;            // 512 float4 slots
            int kk = t4 >> 5, iv = t4 & 31;
            int kg = k0 + kk;
            float4 av, bv4;
            if (kg < 64) {
                av  = *(const float4*)(Qbh + (size_t)kg * Nv + i0 + iv * 4);
                bv4 = *(const float4*)(Kbh + (size_t)kg * Nv + j0 + iv * 4);
            } else {
                int d  = kg - 64;
                int gi = i0 + iv * 4;
                float4 rh = *(const float4*)(relh + ((size_t)h * 64 + d) * 32 + (gi & 31));
                float  rw = relw[((size_t)h * 64 + d) * 32 + (gi >> 5)];
                av = make_float4(rh.x + rw, rh.y + rw, rh.z + rw, rh.w + rw);
                bv4 = *(const float4*)(Qbh + (size_t)d * Nv + j0 + iv * 4);
            }
            float4 ah, al, bhh, bl;
            tf32_split(av.x, ah.x, al.x); tf32_split(av.y, ah.y, al.y);
            tf32_split(av.z, ah.z, al.z); tf32_split(av.w, ah.w, al.w);
            tf32_split(bv4.x, bhh.x, bl.x); tf32_split(bv4.y, bhh.y, bl.y);
            tf32_split(bv4.z, bhh.z, bl.z); tf32_split(bv4.w, bhh.w, bl.w);
            *(float4*)(&AsHi[kk * SA + iv * 4]) = ah;
            *(float4*)(&AsLo[kk * SA + iv * 4]) = al;
            *(float4*)(&BsHi[kk * SA + iv * 4]) = bhh;
            *(float4*)(&BsLo[kk * SA + iv * 4]) = bl;
        }
        __syncthreads();

        // ---- 3 passes: hi*hi, hi*lo, lo*hi ----
        #pragma unroll
        for (int pass = 0; pass < 3; pass++) {
            const float* Ap = (pass < 2) ? AsHi : AsLo;
            const float* Bp = (pass == 1) ? BsLo : BsHi;
            #pragma unroll
            for (int ks = 0; ks < 2; ks++) {
                int kb = ks * 8;
                float a0[2], a1[2], a2[2], a3[2];
                #pragma unroll
                for (int ma = 0; ma < 2; ma++) {
                    int ib = wi + ma * 16 + g;
                    a0[ma] = Ap[(kb + tig) * SA + ib];
                    a1[ma] = Ap[(kb + tig) * SA + ib + 8];
                    a2[ma] = Ap[(kb + tig + 4) * SA + ib];
                    a3[ma] = Ap[(kb + tig + 4) * SA + ib + 8];
                }
                #pragma unroll
                for (int na = 0; na < 8; na++) {
                    int jb = wj + na * 8 + g;
                    float b0 = Bp[(kb + tig) * SA + jb];
                    float b1 = Bp[(kb + tig + 4) * SA + jb];
                    #pragma unroll
                    for (int ma = 0; ma < 2; ma++)
                        mma8(acc[ma][na], a0[ma], a1[ma], a2[ma], a3[ma], b0, b1);
                }
            }
        }
        __syncthreads();
    }

    // ---- epilogue ----
    #pragma unroll
    for (int ma = 0; ma < 2; ma++) {
        int ig = i0 + wi + ma * 16 + g;
        #pragma unroll
        for (int na = 0; na < 8; na++) {
            int jg = j0 + wj + na * 8 + 2 * tig;
            *(float2*)(Lbh + (size_t)ig * Nv + jg)       = make_float2(acc[ma][na][0], acc[ma][na][1]);
            *(float2*)(Lbh + (size_t)(ig + 8) * Nv + jg) = make_float2(acc[ma][na][2], acc[ma][na][3]);
        }
    }
}

// ---------------------------------------------------------------------------
// Kernel 3: row softmax over j (1024 elems/row).
// ---------------------------------------------------------------------------
__global__ void softmax_kernel() {
    const size_t row = blockIdx.x;
    float4* p = (float4*)(g_L + row * Nv);
    const int tid = threadIdx.x;

    float4 v = p[tid];
    float m = fmaxf(fmaxf(v.x, v.y), fmaxf(v.z, v.w));
    #pragma unroll
    for (int o = 16; o; o >>= 1) m = fmaxf(m, __shfl_xor_sync(0xffffffffu, m, o));

    __shared__ float redm[8];
    __shared__ float reds[8];
    if ((tid & 31) == 0) redm[tid >> 5] = m;
    __syncthreads();
    m = redm[0];
    #pragma unroll
    for (int i = 1; i < 8; i++) m = fmaxf(m, redm[i]);

    v.x = __expf(v.x - m); v.y = __expf(v.y - m);
    v.z = __expf(v.z - m); v.w = __expf(v.w - m);
    float s = v.x + v.y + v.z + v.w;
    #pragma unroll
    for (int o = 16; o; o >>= 1) s += __shfl_xor_sync(0xffffffffu, s, o);
    if ((tid & 31) == 0) reds[tid >> 5] = s;
    __syncthreads();
    s = reds[0];
    #pragma unroll
    for (int i = 1; i < 8; i++) s += reds[i];

    float inv = 1.0f / s;
    v.x *= inv; v.y *= inv; v.z *= inv; v.w *= inv;
    p[tid] = v;
}

// ---------------------------------------------------------------------------
// Kernel 4: PV via tensor cores (single-pass tf32, error ~2e-4).
// out[d][m] = sum_n V[d][n] * P[m][n].  A=V (row-major d x n), B=P^T (col-major).
// CTA: 64(d) x 256(m) tile, 8 warps (warp tile 32x64), k(n)-tile 16.
// ---------------------------------------------------------------------------
constexpr int SP = 20;    // smem row stride (floats)
__global__ void __launch_bounds__(256, 2)
pv_mma_kernel(float* __restrict__ out) {
    const int bh = blockIdx.z;
    const int m0 = blockIdx.x * 256;
    const int tid = threadIdx.x;
    const int warp = tid >> 5, lane = tid & 31;
    const int g = lane >> 2, tig = lane & 3;
    const int wd = (warp >> 2) * 32;     // warp d-offset (2)
    const int wm = (warp & 3) * 64;      // warp m-offset (4)

    const float* Vbh = g_V + (size_t)bh * Dv * Nv;
    const float* Pbh = g_L + (size_t)bh * Nv * Nv;

    __shared__ float Vs[64 * SP];
    __shared__ float Ps[256 * SP];

    float acc[2][8][4] = {};

    for (int n0 = 0; n0 < Nv; n0 += 16) {
        // stage V tile 64x16 (1 float4/thread), tf32-rounded
        {
            int t4 = tid;                    // 256 slots = 64 rows x 4 float4
            int d = t4 >> 2, c4 = t4 & 3;
            float4 v = *(const float4*)(Vbh + (size_t)d * Nv + n0 + c4 * 4);
            v.x = tf32_rna(v.x); v.y = tf32_rna(v.y);
            v.z = tf32_rna(v.z); v.w = tf32_rna(v.w);
            *(float4*)(&Vs[d * SP + c4 * 4]) = v;
        }
        // stage P tile 256x16 (4 float4/thread), tf32-rounded
        #pragma unroll
        for (int r = 0; r < 4; r++) {
            int t4 = tid + r * 256;          // 1024 slots = 256 rows x 4 float4
            int mrow = t4 >> 2, c4 = t4 & 3;
            float4 v = *(const float4*)(Pbh + (size_t)(m0 + mrow) * Nv + n0 + c4 * 4);
            v.x = tf32_rna(v.x); v.y = tf32_rna(v.y);
            v.z = tf32_rna(v.z); v.w = tf32_rna(v.w);
            *(float4*)(&Ps[mrow * SP + c4 * 4]) = v;
        }
        __syncthreads();

        #pragma unroll
        for (int ks = 0; ks < 2; ks++) {
            int kb = ks * 8;
            float a0[2], a1[2], a2[2], a3[2];
            #pragma unroll
            for (int ma = 0; ma < 2; ma++) {
                int db = wd + ma * 16 + g;
                a0[ma] = Vs[db * SP + kb + tig];
                a1[ma] = Vs[(db + 8) * SP + kb + tig];
                a2[ma] = Vs[db * SP + kb + tig + 4];
                a3[ma] = Vs[(db + 8) * SP + kb + tig + 4];
            }
            #pragma unroll
            for (int na = 0; na < 8; na++) {
                int mb = wm + na * 8 + g;
                float b0 = Ps[mb * SP + kb + tig];
                float b1 = Ps[mb * SP + kb + tig + 4];
                #pragma unroll
                for (int ma = 0; ma < 2; ma++)
                    mma8(acc[ma][na], a0[ma], a1[ma], a2[ma], a3[ma], b0, b1);
            }
        }
        __syncthreads();
    }

    // epilogue: out[bh*64 + d][m]
    #pragma unroll
    for (int ma = 0; ma < 2; ma++) {
        int dg = wd + ma * 16 + g;
        #pragma unroll
        for (int na = 0; na < 8; na++) {
            int mg = m0 + wm + na * 8 + 2 * tig;
            float* base0 = out + ((size_t)bh * Dv + dg) * Nv + mg;
            float* base1 = out + ((size_t)bh * Dv + dg + 8) * Nv + mg;
            *(float2*)base0 = make_float2(acc[ma][na][0], acc[ma][na][1]);
            *(float2*)base1 = make_float2(acc[ma][na][2], acc[ma][na][3]);
        }
    }
}

// ---------------------------------------------------------------------------
extern "C" void kernel_launch(void* const* d_in, const int* in_sizes, int n_in,
                              void* d_out, int out_size) {
    const float* x    = (const float*)d_in[0];
    const float* Wq   = (const float*)d_in[1];
    const float* bq   = (const float*)d_in[2];
    const float* Wk   = (const float*)d_in[3];
    const float* bk   = (const float*)d_in[4];
    const float* Wv   = (const float*)d_in[5];
    const float* bv   = (const float*)d_in[6];
    const float* relh = (const float*)d_in[7];
    const float* relw = (const float*)d_in[8];
    float* out = (float*)d_out;

    proj_kernel<<<dim3(Nv / 64, 768 / 64, Bv), 256>>>(x, Wq, bq, Wk, bk, Wv, bv);
    logits_mma_kernel<<<dim3(Nv / 128, Nv / 128, Bv * Hv), 256>>>(relh, relw);
    softmax_kernel<<<Bv * Hv * Nv, 256>>>();
    pv_mma_kernel<<<dim3(Nv / 256, 1, Bv * Hv), 256>>>(out);
}

// round 9
// speedup vs baseline: 2.4161x; 2.4161x over previous
#include <cuda_runtime.h>
#include <cuda_bf16.h>
#include <stdint.h>

constexpr int Bv = 16, Hv = 4, Dv = 64, Cv = 256, Nv = 1024;

// ---------------- static device scratch ------------------------------------
__device__ float g_Q[(size_t)Bv * Cv * Nv];
__device__ float g_K[(size_t)Bv * Cv * Nv];
__device__ float g_V[(size_t)Bv * Cv * Nv];
// packed bf16 hi/lo pair arrays (each uint32 = bf16x2 pair)
__device__ uint32_t g_PKh[64 * 64 * 1024], g_PKl[64 * 64 * 1024]; // [bh][k2][n]: k2<32 K-pairs, >=32 Q-pairs
__device__ uint32_t g_Vph[64 * 64 * 512],  g_Vpl[64 * 64 * 512];  // [bh][d][n2]: pairs along n
__device__ uint32_t g_Rph[4 * 32 * 1024],  g_Rpl[4 * 32 * 1024];  // [h][k2][n]: R pairs along d

// ---------------- helpers ---------------------------------------------------
__device__ __forceinline__ uint32_t sptr(const void* p) {
    return (uint32_t)__cvta_generic_to_shared(p);
}
__device__ __forceinline__ void cp16(uint32_t d, const void* s) {
    asm volatile("cp.async.cg.shared.global [%0],[%1],16;\n" :: "r"(d), "l"(s));
}
__device__ __forceinline__ void cpcommit() { asm volatile("cp.async.commit_group;\n"); }
__device__ __forceinline__ void cpwait0()  { asm volatile("cp.async.wait_group 0;\n" ::: "memory"); }

// pack (even,odd) floats -> bf16x2 (even in LOW half, matching mma k-pair order)
__device__ __forceinline__ uint32_t packbf(float e, float o) {
    uint32_t r;
    asm("cvt.rn.bf16x2.f32 %0, %1, %2;" : "=r"(r) : "f"(o), "f"(e));
    return r;
}
__device__ __forceinline__ void split2(float e, float o, uint32_t& h, uint32_t& l) {
    h = packbf(e, o);
    __nv_bfloat162 hb = *reinterpret_cast<__nv_bfloat162*>(&h);
    l = packbf(e - __bfloat162float(hb.x), o - __bfloat162float(hb.y));
}
__device__ __forceinline__ void mma16(float* c, const uint32_t* a, uint32_t b0, uint32_t b1) {
    asm volatile(
        "mma.sync.aligned.m16n8k16.row.col.f32.bf16.bf16.f32 "
        "{%0,%1,%2,%3},{%4,%5,%6,%7},{%8,%9},{%0,%1,%2,%3};\n"
        : "+f"(c[0]), "+f"(c[1]), "+f"(c[2]), "+f"(c[3])
        : "r"(a[0]), "r"(a[1]), "r"(a[2]), "r"(a[3]), "r"(b0), "r"(b1));
}

// ---------------------------------------------------------------------------
// Kernel 1: QKV projection (fp32 SIMT, exact; verified).
// ---------------------------------------------------------------------------
__global__ void proj_kernel(const float* __restrict__ x,
                            const float* __restrict__ Wq, const float* __restrict__ bq,
                            const float* __restrict__ Wk, const float* __restrict__ bk,
                            const float* __restrict__ Wv, const float* __restrict__ bv) {
    const int b  = blockIdx.z;
    const int o0 = blockIdx.y * 64;
    const int n0 = blockIdx.x * 64;
    const int tid = threadIdx.x;
    const int tx = tid & 15, ty = tid >> 4;

    const int which = o0 >> 8;
    const float* W    = (which == 0) ? Wq : (which == 1) ? Wk : Wv;
    const float* bias = (which == 0) ? bq : (which == 1) ? bk : bv;
    float* dst        = (which == 0) ? g_Q : (which == 1) ? g_K : g_V;
    const int or0 = o0 & 255;

    __shared__ float As[16][65];
    __shared__ float Bs[16][64];
    const float* xb = x + (size_t)b * Cv * Nv;

    float acc[4][4] = {};
    for (int k0 = 0; k0 < Cv; k0 += 16) {
        {
            int oo = tid >> 4, kk = tid & 15;
            #pragma unroll
            for (int r = 0; r < 4; r++)
                As[kk][oo + r * 16] = W[(size_t)(or0 + oo + r * 16) * Cv + k0 + kk];
        }
        {
            int nn = tid & 63, kk4 = tid >> 6;
            #pragma unroll
            for (int r = 0; r < 4; r++)
                Bs[kk4 + r * 4][nn] = xb[(size_t)(k0 + kk4 + r * 4) * Nv + n0 + nn];
        }
        __syncthreads();
        #pragma unroll
        for (int kk = 0; kk < 16; kk++) {
            float a[4], bb[4];
            #pragma unroll
            for (int i = 0; i < 4; i++) a[i] = As[kk][ty * 4 + i];
            #pragma unroll
            for (int j = 0; j < 4; j++) bb[j] = Bs[kk][tx * 4 + j];
            #pragma unroll
            for (int i = 0; i < 4; i++)
                #pragma unroll
                for (int j = 0; j < 4; j++)
                    acc[i][j] += a[i] * bb[j];
        }
        __syncthreads();
    }
    #pragma unroll
    for (int i = 0; i < 4; i++) {
        int orow = or0 + ty * 4 + i;
        float bval = bias[orow];
        float* drow = dst + ((size_t)b * Cv + orow) * Nv + n0 + tx * 4;
        #pragma unroll
        for (int j = 0; j < 4; j++) drow[j] = acc[i][j] + bval;
    }
}

// ---------------------------------------------------------------------------
// Kernel 2: pack K/Q (pairs along d), V (pairs along n), R (pairs along d)
// into bf16 hi/lo uint32 arrays.
// ---------------------------------------------------------------------------
__global__ void pack_kernel(const float* __restrict__ relh, const float* __restrict__ relw) {
    const int t0 = blockIdx.x * blockDim.x + threadIdx.x;
    const int stride = gridDim.x * blockDim.x;
    for (int i = t0; i < 64 * 64 * 1024; i += stride) {
        int n = i & 1023, k2 = (i >> 10) & 63, bh = i >> 16;
        const float* s = (k2 < 32) ? g_K + ((size_t)bh * 64 + 2 * k2) * 1024
                                   : g_Q + ((size_t)bh * 64 + 2 * (k2 - 32)) * 1024;
        uint32_t h, l;
        split2(s[n], s[n + 1024], h, l);
        g_PKh[i] = h; g_PKl[i] = l;
    }
    for (int i = t0; i < 64 * 64 * 512; i += stride) {
        int n2 = i & 511, d = (i >> 9) & 63, bh = i >> 15;
        const float* s = g_V + ((size_t)bh * 64 + d) * 1024 + 2 * n2;
        uint32_t h, l;
        split2(s[0], s[1], h, l);
        g_Vph[i] = h; g_Vpl[i] = l;
    }
    for (int i = t0; i < 4 * 32 * 1024; i += stride) {
        int n = i & 1023, k2 = (i >> 10) & 31, hh = i >> 15;
        int d = 2 * k2;
        float e = relh[(hh * 64 + d) * 32 + (n & 31)]     + relw[(hh * 64 + d) * 32 + (n >> 5)];
        float o = relh[(hh * 64 + d + 1) * 32 + (n & 31)] + relw[(hh * 64 + d + 1) * 32 + (n >> 5)];
        uint32_t h, l;
        split2(e, o, h, l);
        g_Rph[i] = h; g_Rpl[i] = l;
    }
}

// ---------------------------------------------------------------------------
// Kernel 3: fused flash attention.
// CTA = (bh, 128 queries). 8 warps x 16 queries. j streamed in 64-wide tiles.
// ---------------------------------------------------------------------------
// smem layout (uint32 units):
constexpr int OFF_AH = 0;                 // A hi: [64 k2][128 i] stride 136
constexpr int OFF_AL = 8704;              // A lo
constexpr int OFF_B  = 17408;             // [buf]{hi,lo}: [64 k2][64 j] stride 72
constexpr int BUFB   = 9216;              // per-buf (hi 4608 + lo 4608)
constexpr int OFF_V  = 35840;             // [buf]{hi,lo}: [64 d][32 n2] stride 40
constexpr int BUFV   = 5120;              // per-buf (hi 2560 + lo 2560)
constexpr int SM_U32 = 46080;             // 184320 bytes

__global__ void __launch_bounds__(256, 1)
attn_fused(float* __restrict__ out) {
    extern __shared__ uint32_t sm[];
    const int bh = blockIdx.y, h = bh & 3;
    const int i0 = blockIdx.x * 128;
    const int tid = threadIdx.x, lane = tid & 31, warp = tid >> 5;
    const int g = lane >> 2, tig = lane & 3;
    const int iw = warp * 16;

    // ---- stage resident A = [Q;R] hi/lo (4096 16B chunks) ----
    #pragma unroll
    for (int it = 0; it < 16; it++) {
        int c = tid + it * 256;
        int hl = c >> 11, r = (c >> 5) & 63, ch = c & 31;
        const uint32_t* src = (r < 32)
            ? (hl ? g_PKl : g_PKh) + ((size_t)bh * 64 + 32 + r) * 1024 + i0 + ch * 4
            : (hl ? g_Rpl : g_Rph) + ((size_t)h * 32 + (r - 32)) * 1024 + i0 + ch * 4;
        cp16(sptr(sm + (hl ? OFF_AL : OFF_AH) + r * 136 + ch * 4), src);
    }
    // ---- stage B/V tile helper ----
    auto stageBV = [&](int jt, int buf) {
        #pragma unroll
        for (int it = 0; it < 8; it++) {                    // B: 2048 chunks
            int c = tid + it * 256;
            int hl = c >> 10, r = (c >> 4) & 63, ch = c & 15;
            const uint32_t* src = (hl ? g_PKl : g_PKh) +
                ((size_t)bh * 64 + r) * 1024 + jt * 64 + ch * 4;
            cp16(sptr(sm + OFF_B + buf * BUFB + hl * 4608 + r * 72 + ch * 4), src);
        }
        #pragma unroll
        for (int it = 0; it < 4; it++) {                    // V: 1024 chunks
            int c = tid + it * 256;
            int hl = c >> 9, r = (c >> 3) & 63, ch = c & 7;
            const uint32_t* src = (hl ? g_Vpl : g_Vph) +
                ((size_t)bh * 64 + r) * 512 + jt * 32 + ch * 4;
            cp16(sptr(sm + OFF_V + buf * BUFV + hl * 2560 + r * 40 + ch * 4), src);
        }
    };
    stageBV(0, 0);
    cpcommit();

    float m0 = -1e30f, m1 = -1e30f, s0 = 0.f, s1 = 0.f;
    float Oa[4][2][4] = {};

    for (int jt = 0; jt < 16; jt++) {
        cpwait0();
        __syncthreads();
        if (jt < 15) { stageBV(jt + 1, (jt + 1) & 1); cpcommit(); }
        const int bb = OFF_B + (jt & 1) * BUFB;
        const int vb = OFF_V + (jt & 1) * BUFV;

        // ---- S = [Q;R]^T [K;Q] over k=128 (3-pass bf16) ----
        float sacc[8][4] = {};
        #pragma unroll
        for (int kc = 0; kc < 8; kc++) {
            uint32_t Ah[4], Al[4];
            int ab = (kc * 8 + tig) * 136 + iw + g;
            Ah[0] = sm[OFF_AH + ab];           Ah[1] = sm[OFF_AH + ab + 8];
            Ah[2] = sm[OFF_AH + ab + 4 * 136]; Ah[3] = sm[OFF_AH + ab + 4 * 136 + 8];
            Al[0] = sm[OFF_AL + ab];           Al[1] = sm[OFF_AL + ab + 8];
            Al[2] = sm[OFF_AL + ab + 4 * 136]; Al[3] = sm[OFF_AL + ab + 4 * 136 + 8];
            #pragma unroll
            for (int na = 0; na < 8; na++) {
                int bidx = (kc * 8 + tig) * 72 + na * 8 + g;
                uint32_t b0h = sm[bb + bidx],        b1h = sm[bb + bidx + 4 * 72];
                uint32_t b0l = sm[bb + 4608 + bidx], b1l = sm[bb + 4608 + bidx + 4 * 72];
                mma16(sacc[na], Ah, b0h, b1h);
                mma16(sacc[na], Ah, b0l, b1l);
                mma16(sacc[na], Al, b0h, b1h);
            }
        }

        // ---- online softmax (rows: g -> half0, g+8 -> half1) ----
        float tm0 = -1e30f, tm1 = -1e30f;
        #pragma unroll
        for (int na = 0; na < 8; na++) {
            tm0 = fmaxf(tm0, fmaxf(sacc[na][0], sacc[na][1]));
            tm1 = fmaxf(tm1, fmaxf(sacc[na][2], sacc[na][3]));
        }
        tm0 = fmaxf(tm0, __shfl_xor_sync(0xffffffffu, tm0, 1));
        tm0 = fmaxf(tm0, __shfl_xor_sync(0xffffffffu, tm0, 2));
        tm1 = fmaxf(tm1, __shfl_xor_sync(0xffffffffu, tm1, 1));
        tm1 = fmaxf(tm1, __shfl_xor_sync(0xffffffffu, tm1, 2));
        float mn0 = fmaxf(m0, tm0), mn1 = fmaxf(m1, tm1);
        float sc0 = __expf(m0 - mn0), sc1 = __expf(m1 - mn1);
        m0 = mn0; m1 = mn1;

        float ps0 = 0.f, ps1 = 0.f;
        #pragma unroll
        for (int na = 0; na < 8; na++) {
            sacc[na][0] = __expf(sacc[na][0] - m0);
            sacc[na][1] = __expf(sacc[na][1] - m0);
            sacc[na][2] = __expf(sacc[na][2] - m1);
            sacc[na][3] = __expf(sacc[na][3] - m1);
            ps0 += sacc[na][0] + sacc[na][1];
            ps1 += sacc[na][2] + sacc[na][3];
        }
        s0 = s0 * sc0 + ps0;
        s1 = s1 * sc1 + ps1;

        // broadcast per-query O rescale factors (query i = 8*ni + 2*tig [+1])
        float f0 = __shfl_sync(0xffffffffu, sc0, 8 * tig);
        float f1 = __shfl_sync(0xffffffffu, sc0, 8 * tig + 4);
        float q0 = __shfl_sync(0xffffffffu, sc1, 8 * tig);
        float q1 = __shfl_sync(0xffffffffu, sc1, 8 * tig + 4);
        #pragma unroll
        for (int ma = 0; ma < 4; ma++) {
            Oa[ma][0][0] *= f0; Oa[ma][0][1] *= f1; Oa[ma][0][2] *= f0; Oa[ma][0][3] *= f1;
            Oa[ma][1][0] *= q0; Oa[ma][1][1] *= q1; Oa[ma][1][2] *= q0; Oa[ma][1][3] *= q1;
        }

        // ---- O += V * P^T : A=V (m=d16), B=P from S-acc register identity ----
        #pragma unroll
        for (int kc = 0; kc < 4; kc++) {
            uint32_t bh00, bl00, bh01, bl01, bh80, bl80, bh81, bl81;
            split2(sacc[2 * kc][0],     sacc[2 * kc][1],     bh00, bl00);
            split2(sacc[2 * kc + 1][0], sacc[2 * kc + 1][1], bh01, bl01);
            split2(sacc[2 * kc][2],     sacc[2 * kc][3],     bh80, bl80);
            split2(sacc[2 * kc + 1][2], sacc[2 * kc + 1][3], bh81, bl81);
            #pragma unroll
            for (int ma = 0; ma < 4; ma++) {
                uint32_t Vh[4], Vl[4];
                int vx = (ma * 16 + g) * 40 + kc * 8 + tig;
                Vh[0] = sm[vb + vx];          Vh[1] = sm[vb + vx + 8 * 40];
                Vh[2] = sm[vb + vx + 4];      Vh[3] = sm[vb + vx + 8 * 40 + 4];
                Vl[0] = sm[vb + 2560 + vx];   Vl[1] = sm[vb + 2560 + vx + 8 * 40];
                Vl[2] = sm[vb + 2560 + vx + 4]; Vl[3] = sm[vb + 2560 + vx + 8 * 40 + 4];
                mma16(Oa[ma][0], Vh, bh00, bh01);
                mma16(Oa[ma][0], Vh, bl00, bl01);
                mma16(Oa[ma][0], Vl, bh00, bh01);
                mma16(Oa[ma][1], Vh, bh80, bh81);
                mma16(Oa[ma][1], Vh, bl80, bl81);
                mma16(Oa[ma][1], Vl, bh80, bh81);
            }
        }
    }

    // ---- epilogue: normalize, transpose through smem, coalesced store ----
    s0 += __shfl_xor_sync(0xffffffffu, s0, 1);
    s0 += __shfl_xor_sync(0xffffffffu, s0, 2);
    s1 += __shfl_xor_sync(0xffffffffu, s1, 1);
    s1 += __shfl_xor_sync(0xffffffffu, s1, 2);
    float i00 = 1.f / __shfl_sync(0xffffffffu, s0, 8 * tig);
    float i01 = 1.f / __shfl_sync(0xffffffffu, s0, 8 * tig + 4);
    float i10 = 1.f / __shfl_sync(0xffffffffu, s1, 8 * tig);
    float i11 = 1.f / __shfl_sync(0xffffffffu, s1, 8 * tig + 4);

    __syncthreads();                      // done with B/V smem; reuse as Osm
    float* Of = (float*)(sm + OFF_B);     // [64 d][stride 132] floats
    #pragma unroll
    for (int ma = 0; ma < 4; ma++) {
        int d0 = ma * 16 + g;
        #pragma unroll
        for (int ni = 0; ni < 2; ni++) {
            float ie = ni ? i10 : i00, io = ni ? i11 : i01;
            int col = iw + ni * 8 + 2 * tig;
            Of[d0 * 132 + col]           = Oa[ma][ni][0] * ie;
            Of[d0 * 132 + col + 1]       = Oa[ma][ni][1] * io;
            Of[(d0 + 8) * 132 + col]     = Oa[ma][ni][2] * ie;
            Of[(d0 + 8) * 132 + col + 1] = Oa[ma][ni][3] * io;
        }
    }
    __syncthreads();
    #pragma unroll
    for (int it = 0; it < 8; it++) {      // 2048 float4 stores
        int c = tid + it * 256;
        int row = c >> 5, col4 = c & 31;
        float4 v = *(float4*)(Of + row * 132 + col4 * 4);
        *(float4*)(out + ((size_t)bh * 64 + row) * 1024 + i0 + col4 * 4) = v;
    }
}

// ---------------------------------------------------------------------------
extern "C" void kernel_launch(void* const* d_in, const int* in_sizes, int n_in,
                              void* d_out, int out_size) {
    const float* x    = (const float*)d_in[0];
    const float* Wq   = (const float*)d_in[1];
    const float* bq   = (const float*)d_in[2];
    const float* Wk   = (const float*)d_in[3];
    const float* bk   = (const float*)d_in[4];
    const float* Wv   = (const float*)d_in[5];
    const float* bv   = (const float*)d_in[6];
    const float* relh = (const float*)d_in[7];
    const float* relw = (const float*)d_in[8];
    float* out = (float*)d_out;

    cudaFuncSetAttribute(attn_fused, cudaFuncAttributeMaxDynamicSharedMemorySize,
                         SM_U32 * 4);

    proj_kernel<<<dim3(Nv / 64, 768 / 64, Bv), 256>>>(x, Wq, bq, Wk, bk, Wv, bv);
    pack_kernel<<<4096, 256>>>(relh, relw);
    attn_fused<<<dim3(8, 64), 256, SM_U32 * 4>>>(out);
}

// round 10
// speedup vs baseline: 3.2838x; 1.3591x over previous
#include <cuda_runtime.h>
#include <cuda_bf16.h>
#include <stdint.h>

constexpr int Bv = 16, Hv = 4, Dv = 64, Cv = 256, Nv = 1024;

// ---------------- static device scratch ------------------------------------
// packed bf16 hi/lo pair arrays (each uint32 = bf16x2 pair)
__device__ uint32_t g_PKh[64 * 64 * 1024], g_PKl[64 * 64 * 1024]; // [bh][k2][n]: k2<32 K-pairs, >=32 Q-pairs
__device__ uint32_t g_Vph[64 * 64 * 512],  g_Vpl[64 * 64 * 512];  // [bh][d][n2]: pairs along n
__device__ uint32_t g_Rph[4 * 32 * 1024],  g_Rpl[4 * 32 * 1024];  // [h][k2][n]: R pairs along d
__device__ uint32_t g_xPh[16 * 128 * 1024], g_xPl[16 * 128 * 1024]; // [b][k2][n]: x pairs along channel
__device__ uint32_t g_WPh[128 * 768], g_WPl[128 * 768];             // [k2][o]: Wcat pairs along input channel

// ---------------- helpers ---------------------------------------------------
__device__ __forceinline__ uint32_t sptr(const void* p) {
    return (uint32_t)__cvta_generic_to_shared(p);
}
__device__ __forceinline__ void cp16(uint32_t d, const void* s) {
    asm volatile("cp.async.cg.shared.global [%0],[%1],16;\n" :: "r"(d), "l"(s));
}
__device__ __forceinline__ void cpcommit() { asm volatile("cp.async.commit_group;\n"); }
__device__ __forceinline__ void cpwait0()  { asm volatile("cp.async.wait_group 0;\n" ::: "memory"); }

// pack (even,odd) floats -> bf16x2 (even in LOW half, matching mma k-pair order)
__device__ __forceinline__ uint32_t packbf(float e, float o) {
    uint32_t r;
    asm("cvt.rn.bf16x2.f32 %0, %1, %2;" : "=r"(r) : "f"(o), "f"(e));
    return r;
}
__device__ __forceinline__ void split2(float e, float o, uint32_t& h, uint32_t& l) {
    h = packbf(e, o);
    __nv_bfloat162 hb = *reinterpret_cast<__nv_bfloat162*>(&h);
    l = packbf(e - __bfloat162float(hb.x), o - __bfloat162float(hb.y));
}
__device__ __forceinline__ void mma16(float* c, const uint32_t* a, uint32_t b0, uint32_t b1) {
    asm volatile(
        "mma.sync.aligned.m16n8k16.row.col.f32.bf16.bf16.f32 "
        "{%0,%1,%2,%3},{%4,%5,%6,%7},{%8,%9},{%0,%1,%2,%3};\n"
        : "+f"(c[0]), "+f"(c[1]), "+f"(c[2]), "+f"(c[3])
        : "r"(a[0]), "r"(a[1]), "r"(a[2]), "r"(a[3]), "r"(b0), "r"(b1));
}

// ---------------------------------------------------------------------------
// Kernel 0: split x and Wcat into bf16 hi/lo pair arrays.
// ---------------------------------------------------------------------------
__global__ void split_xw(const float* __restrict__ x,
                         const float* __restrict__ Wq, const float* __restrict__ Wk,
                         const float* __restrict__ Wv) {
    const int t0 = blockIdx.x * blockDim.x + threadIdx.x;
    const int stride = gridDim.x * blockDim.x;
    for (int i = t0; i < 16 * 128 * 1024; i += stride) {
        int n = i & 1023, k2 = (i >> 10) & 127, b = i >> 17;
        const float* s = x + ((size_t)b * 256 + 2 * k2) * 1024 + n;
        uint32_t h, l;
        split2(s[0], s[1024], h, l);
        g_xPh[i] = h; g_xPl[i] = l;
    }
    for (int i = t0; i < 128 * 768; i += stride) {
        int o = i % 768, k2 = i / 768;
        int which = o >> 8, row = o & 255;
        const float* W = (which == 0) ? Wq : (which == 1) ? Wk : Wv;
        uint32_t h, l;
        split2(W[row * 256 + 2 * k2], W[row * 256 + 2 * k2 + 1], h, l);
        g_WPh[i] = h; g_WPl[i] = l;
    }
}

// ---------------------------------------------------------------------------
// Kernel 1: pack R = rel_h + rel_w into bf16 hi/lo pairs along d.
// ---------------------------------------------------------------------------
__global__ void pack_rel(const float* __restrict__ relh, const float* __restrict__ relw) {
    const int t0 = blockIdx.x * blockDim.x + threadIdx.x;
    const int stride = gridDim.x * blockDim.x;
    for (int i = t0; i < 4 * 32 * 1024; i += stride) {
        int n = i & 1023, k2 = (i >> 10) & 31, hh = i >> 15;
        int d = 2 * k2;
        float e = relh[(hh * 64 + d) * 32 + (n & 31)]     + relw[(hh * 64 + d) * 32 + (n >> 5)];
        float o = relh[(hh * 64 + d + 1) * 32 + (n & 31)] + relw[(hh * 64 + d + 1) * 32 + (n >> 5)];
        uint32_t h, l;
        split2(e, o, h, l);
        g_Rph[i] = h; g_Rpl[i] = l;
    }
}

// ---------------------------------------------------------------------------
// Kernel 2: QKV projection via bf16 3-pass mma, packing epilogue.
// CTA 128(o) x 128(n), k=256 in 4 double-buffered stages of 64.
// smem buffer (u32): [buf]{WH 32x136, WL, XH, XL} ; buf size 17408, total 34816.
// ---------------------------------------------------------------------------
constexpr int PJ_BUF = 17408;
constexpr int PJ_U32 = 2 * PJ_BUF;        // 139264 bytes

__global__ void __launch_bounds__(256, 1)
proj_mma(const float* __restrict__ bq, const float* __restrict__ bk,
         const float* __restrict__ bv) {
    extern __shared__ uint32_t sm[];
    const int b  = blockIdx.z;
    const int o0 = blockIdx.y * 128;          // 0..640 over concat 768
    const int n0 = blockIdx.x * 128;
    const int tid = threadIdx.x, lane = tid & 31, warp = tid >> 5;
    const int g = lane >> 2, tig = lane & 3;
    const int iw = warp * 16;
    const int which = o0 >> 8;                // 0:Q 1:K 2:V
    const int or0 = o0 & 255;

    auto stage = [&](int s, int buf) {
        int base = buf * PJ_BUF;
        #pragma unroll
        for (int it = 0; it < 8; it++) {      // W hi/lo: 2048 16B chunks
            int c = tid + it * 256;
            int hl = c >> 10, r = (c >> 5) & 31, ch = c & 31;
            const uint32_t* src = (hl ? g_WPl : g_WPh) + (s * 32 + r) * 768 + o0 + ch * 4;
            cp16(sptr(sm + base + hl * 4352 + r * 136 + ch * 4), src);
        }
        #pragma unroll
        for (int it = 0; it < 8; it++) {      // x hi/lo: 2048 16B chunks
            int c = tid + it * 256;
            int hl = c >> 10, r = (c >> 5) & 31, ch = c & 31;
            const uint32_t* src = (hl ? g_xPl : g_xPh) +
                ((size_t)(b * 128 + s * 32 + r)) * 1024 + n0 + ch * 4;
            cp16(sptr(sm + base + 8704 + hl * 4352 + r * 136 + ch * 4), src);
        }
    };
    stage(0, 0);
    cpcommit();

    float acc[16][4] = {};
    for (int s = 0; s < 4; s++) {
        cpwait0();
        __syncthreads();
        if (s < 3) { stage(s + 1, (s + 1) & 1); cpcommit(); }
        const int W0 = (s & 1) * PJ_BUF;
        const int X0 = W0 + 8704;
        #pragma unroll
        for (int kc = 0; kc < 4; kc++) {
            uint32_t Ah[4], Al[4];
            int ab = W0 + (kc * 8 + tig) * 136 + iw + g;
            Ah[0] = sm[ab];           Ah[1] = sm[ab + 8];
            Ah[2] = sm[ab + 4 * 136]; Ah[3] = sm[ab + 4 * 136 + 8];
            Al[0] = sm[ab + 4352];           Al[1] = sm[ab + 4352 + 8];
            Al[2] = sm[ab + 4352 + 4 * 136]; Al[3] = sm[ab + 4352 + 4 * 136 + 8];
            #pragma unroll
            for (int na = 0; na < 16; na++) {
                int bx = X0 + (kc * 8 + tig) * 136 + na * 8 + g;
                uint32_t b0h = sm[bx],        b1h = sm[bx + 4 * 136];
                uint32_t b0l = sm[bx + 4352], b1l = sm[bx + 4352 + 4 * 136];
                mma16(acc[na], Ah, b0h, b1h);
                mma16(acc[na], Ah, b0l, b1l);
                mma16(acc[na], Al, b0h, b1h);
            }
        }
        __syncthreads();
    }

    if (which == 2) {
        // ---- V: pairs along n come straight from adjacent accumulator cols ----
        #pragma unroll
        for (int na = 0; na < 16; na++) {
            int colE = n0 + na * 8 + 2 * tig;
            int ch0 = or0 + iw + g;
            float bb0 = bv[ch0], bb8 = bv[ch0 + 8];
            uint32_t h, l;
            split2(acc[na][0] + bb0, acc[na][1] + bb0, h, l);
            size_t i0v = ((size_t)(b * 4 + (ch0 >> 6)) * 64 + (ch0 & 63)) * 512 + (colE >> 1);
            g_Vph[i0v] = h; g_Vpl[i0v] = l;
            int ch1 = ch0 + 8;
            split2(acc[na][2] + bb8, acc[na][3] + bb8, h, l);
            size_t i1v = ((size_t)(b * 4 + (ch1 >> 6)) * 64 + (ch1 & 63)) * 512 + (colE >> 1);
            g_Vph[i1v] = h; g_Vpl[i1v] = l;
        }
    } else {
        // ---- Q/K: pairs along d need a transpose through smem ----
        const float* bias = (which == 0) ? bq : bk;
        float* Of = (float*)sm;               // [128][132] floats
        #pragma unroll
        for (int na = 0; na < 16; na++) {
            int row0 = iw + g, col = na * 8 + 2 * tig;
            float bb0 = bias[or0 + row0], bb8 = bias[or0 + row0 + 8];
            Of[row0 * 132 + col]           = acc[na][0] + bb0;
            Of[row0 * 132 + col + 1]       = acc[na][1] + bb0;
            Of[(row0 + 8) * 132 + col]     = acc[na][2] + bb8;
            Of[(row0 + 8) * 132 + col + 1] = acc[na][3] + bb8;
        }
        __syncthreads();
        const int k2off = (which == 0) ? 32 : 0;
        #pragma unroll
        for (int it = 0; it < 32; it++) {     // 8192 pairs
            int c = tid + it * 256;
            int n = c & 127, k2l = c >> 7;    // k2l 0..63
            float e = Of[(2 * k2l) * 132 + n];
            float o = Of[(2 * k2l + 1) * 132 + n];
            uint32_t h, l;
            split2(e, o, h, l);
            int ch = or0 + 2 * k2l;
            size_t idx = ((size_t)(b * 4 + (ch >> 6)) * 64 + k2off + ((ch & 63) >> 1)) * 1024 + n0 + n;
            g_PKh[idx] = h; g_PKl[idx] = l;
        }
    }
}

// ---------------------------------------------------------------------------
// Kernel 3: fused flash attention (unchanged from R9 passing version).
// ---------------------------------------------------------------------------
constexpr int OFF_AH = 0;                 // A hi: [64 k2][128 i] stride 136
constexpr int OFF_AL = 8704;              // A lo
constexpr int OFF_B  = 17408;             // [buf]{hi,lo}: [64 k2][64 j] stride 72
constexpr int BUFB   = 9216;
constexpr int OFF_V  = 35840;             // [buf]{hi,lo}: [64 d][32 n2] stride 40
constexpr int BUFV   = 5120;
constexpr int SM_U32 = 46080;             // 184320 bytes

__global__ void __launch_bounds__(256, 1)
attn_fused(float* __restrict__ out) {
    extern __shared__ uint32_t sm[];
    const int bh = blockIdx.y, h = bh & 3;
    const int i0 = blockIdx.x * 128;
    const int tid = threadIdx.x, lane = tid & 31, warp = tid >> 5;
    const int g = lane >> 2, tig = lane & 3;
    const int iw = warp * 16;

    #pragma unroll
    for (int it = 0; it < 16; it++) {
        int c = tid + it * 256;
        int hl = c >> 11, r = (c >> 5) & 63, ch = c & 31;
        const uint32_t* src = (r < 32)
            ? (hl ? g_PKl : g_PKh) + ((size_t)bh * 64 + 32 + r) * 1024 + i0 + ch * 4
            : (hl ? g_Rpl : g_Rph) + ((size_t)h * 32 + (r - 32)) * 1024 + i0 + ch * 4;
        cp16(sptr(sm + (hl ? OFF_AL : OFF_AH) + r * 136 + ch * 4), src);
    }
    auto stageBV = [&](int jt, int buf) {
        #pragma unroll
        for (int it = 0; it < 8; it++) {
            int c = tid + it * 256;
            int hl = c >> 10, r = (c >> 4) & 63, ch = c & 15;
            const uint32_t* src = (hl ? g_PKl : g_PKh) +
                ((size_t)bh * 64 + r) * 1024 + jt * 64 + ch * 4;
            cp16(sptr(sm + OFF_B + buf * BUFB + hl * 4608 + r * 72 + ch * 4), src);
        }
        #pragma unroll
        for (int it = 0; it < 4; it++) {
            int c = tid + it * 256;
            int hl = c >> 9, r = (c >> 3) & 63, ch = c & 7;
            const uint32_t* src = (hl ? g_Vpl : g_Vph) +
                ((size_t)bh * 64 + r) * 512 + jt * 32 + ch * 4;
            cp16(sptr(sm + OFF_V + buf * BUFV + hl * 2560 + r * 40 + ch * 4), src);
        }
    };
    stageBV(0, 0);
    cpcommit();

    float m0 = -1e30f, m1 = -1e30f, s0 = 0.f, s1 = 0.f;
    float Oa[4][2][4] = {};

    for (int jt = 0; jt < 16; jt++) {
        cpwait0();
        __syncthreads();
        if (jt < 15) { stageBV(jt + 1, (jt + 1) & 1); cpcommit(); }
        const int bb = OFF_B + (jt & 1) * BUFB;
        const int vb = OFF_V + (jt & 1) * BUFV;

        float sacc[8][4] = {};
        #pragma unroll
        for (int kc = 0; kc < 8; kc++) {
            uint32_t Ah[4], Al[4];
            int ab = (kc * 8 + tig) * 136 + iw + g;
            Ah[0] = sm[OFF_AH + ab];           Ah[1] = sm[OFF_AH + ab + 8];
            Ah[2] = sm[OFF_AH + ab + 4 * 136]; Ah[3] = sm[OFF_AH + ab + 4 * 136 + 8];
            Al[0] = sm[OFF_AL + ab];           Al[1] = sm[OFF_AL + ab + 8];
            Al[2] = sm[OFF_AL + ab + 4 * 136]; Al[3] = sm[OFF_AL + ab + 4 * 136 + 8];
            #pragma unroll
            for (int na = 0; na < 8; na++) {
                int bidx = (kc * 8 + tig) * 72 + na * 8 + g;
                uint32_t b0h = sm[bb + bidx],        b1h = sm[bb + bidx + 4 * 72];
                uint32_t b0l = sm[bb + 4608 + bidx], b1l = sm[bb + 4608 + bidx + 4 * 72];
                mma16(sacc[na], Ah, b0h, b1h);
                mma16(sacc[na], Ah, b0l, b1l);
                mma16(sacc[na], Al, b0h, b1h);
            }
        }

        float tm0 = -1e30f, tm1 = -1e30f;
        #pragma unroll
        for (int na = 0; na < 8; na++) {
            tm0 = fmaxf(tm0, fmaxf(sacc[na][0], sacc[na][1]));
            tm1 = fmaxf(tm1, fmaxf(sacc[na][2], sacc[na][3]));
        }
        tm0 = fmaxf(tm0, __shfl_xor_sync(0xffffffffu, tm0, 1));
        tm0 = fmaxf(tm0, __shfl_xor_sync(0xffffffffu, tm0, 2));
        tm1 = fmaxf(tm1, __shfl_xor_sync(0xffffffffu, tm1, 1));
        tm1 = fmaxf(tm1, __shfl_xor_sync(0xffffffffu, tm1, 2));
        float mn0 = fmaxf(m0, tm0), mn1 = fmaxf(m1, tm1);
        float sc0 = __expf(m0 - mn0), sc1 = __expf(m1 - mn1);
        m0 = mn0; m1 = mn1;

        float ps0 = 0.f, ps1 = 0.f;
        #pragma unroll
        for (int na = 0; na < 8; na++) {
            sacc[na][0] = __expf(sacc[na][0] - m0);
            sacc[na][1] = __expf(sacc[na][1] - m0);
            sacc[na][2] = __expf(sacc[na][2] - m1);
            sacc[na][3] = __expf(sacc[na][3] - m1);
            ps0 += sacc[na][0] + sacc[na][1];
            ps1 += sacc[na][2] + sacc[na][3];
        }
        s0 = s0 * sc0 + ps0;
        s1 = s1 * sc1 + ps1;

        float f0 = __shfl_sync(0xffffffffu, sc0, 8 * tig);
        float f1 = __shfl_sync(0xffffffffu, sc0, 8 * tig + 4);
        float q0 = __shfl_sync(0xffffffffu, sc1, 8 * tig);
        float q1 = __shfl_sync(0xffffffffu, sc1, 8 * tig + 4);
        #pragma unroll
        for (int ma = 0; ma < 4; ma++) {
            Oa[ma][0][0] *= f0; Oa[ma][0][1] *= f1; Oa[ma][0][2] *= f0; Oa[ma][0][3] *= f1;
            Oa[ma][1][0] *= q0; Oa[ma][1][1] *= q1; Oa[ma][1][2] *= q0; Oa[ma][1][3] *= q1;
        }

        #pragma unroll
        for (int kc = 0; kc < 4; kc++) {
            uint32_t bh00, bl00, bh01, bl01, bh80, bl80, bh81, bl81;
            split2(sacc[2 * kc][0],     sacc[2 * kc][1],     bh00, bl00);
            split2(sacc[2 * kc + 1][0], sacc[2 * kc + 1][1], bh01, bl01);
            split2(sacc[2 * kc][2],     sacc[2 * kc][3],     bh80, bl80);
            split2(sacc[2 * kc + 1][2], sacc[2 * kc + 1][3], bh81, bl81);
            #pragma unroll
            for (int ma = 0; ma < 4; ma++) {
                uint32_t Vh[4], Vl[4];
                int vx = (ma * 16 + g) * 40 + kc * 8 + tig;
                Vh[0] = sm[vb + vx];          Vh[1] = sm[vb + vx + 8 * 40];
                Vh[2] = sm[vb + vx + 4];      Vh[3] = sm[vb + vx + 8 * 40 + 4];
                Vl[0] = sm[vb + 2560 + vx];   Vl[1] = sm[vb + 2560 + vx + 8 * 40];
                Vl[2] = sm[vb + 2560 + vx + 4]; Vl[3] = sm[vb + 2560 + vx + 8 * 40 + 4];
                mma16(Oa[ma][0], Vh, bh00, bh01);
                mma16(Oa[ma][0], Vh, bl00, bl01);
                mma16(Oa[ma][0], Vl, bh00, bh01);
                mma16(Oa[ma][1], Vh, bh80, bh81);
                mma16(Oa[ma][1], Vh, bl80, bl81);
                mma16(Oa[ma][1], Vl, bh80, bh81);
            }
        }
    }

    s0 += __shfl_xor_sync(0xffffffffu, s0, 1);
    s0 += __shfl_xor_sync(0xffffffffu, s0, 2);
    s1 += __shfl_xor_sync(0xffffffffu, s1, 1);
    s1 += __shfl_xor_sync(0xffffffffu, s1, 2);
    float i00 = 1.f / __shfl_sync(0xffffffffu, s0, 8 * tig);
    float i01 = 1.f / __shfl_sync(0xffffffffu, s0, 8 * tig + 4);
    float i10 = 1.f / __shfl_sync(0xffffffffu, s1, 8 * tig);
    float i11 = 1.f / __shfl_sync(0xffffffffu, s1, 8 * tig + 4);

    __syncthreads();
    float* Of = (float*)(sm + OFF_B);
    #pragma unroll
    for (int ma = 0; ma < 4; ma++) {
        int d0 = ma * 16 + g;
        #pragma unroll
        for (int ni = 0; ni < 2; ni++) {
            float ie = ni ? i10 : i00, io = ni ? i11 : i01;
            int col = iw + ni * 8 + 2 * tig;
            Of[d0 * 132 + col]           = Oa[ma][ni][0] * ie;
            Of[d0 * 132 + col + 1]       = Oa[ma][ni][1] * io;
            Of[(d0 + 8) * 132 + col]     = Oa[ma][ni][2] * ie;
            Of[(d0 + 8) * 132 + col + 1] = Oa[ma][ni][3] * io;
        }
    }
    __syncthreads();
    #pragma unroll
    for (int it = 0; it < 8; it++) {
        int c = tid + it * 256;
        int row = c >> 5, col4 = c & 31;
        float4 v = *(float4*)(Of + row * 132 + col4 * 4);
        *(float4*)(out + ((size_t)bh * 64 + row) * 1024 + i0 + col4 * 4) = v;
    }
}

// ---------------------------------------------------------------------------
extern "C" void kernel_launch(void* const* d_in, const int* in_sizes, int n_in,
                              void* d_out, int out_size) {
    const float* x    = (const float*)d_in[0];
    const float* Wq   = (const float*)d_in[1];
    const float* bq   = (const float*)d_in[2];
    const float* Wk   = (const float*)d_in[3];
    const float* bk   = (const float*)d_in[4];
    const float* Wv   = (const float*)d_in[5];
    const float* bv   = (const float*)d_in[6];
    const float* relh = (const float*)d_in[7];
    const float* relw = (const float*)d_in[8];
    float* out = (float*)d_out;

    cudaFuncSetAttribute(proj_mma, cudaFuncAttributeMaxDynamicSharedMemorySize,
                         PJ_U32 * 4);
    cudaFuncSetAttribute(attn_fused, cudaFuncAttributeMaxDynamicSharedMemorySize,
                         SM_U32 * 4);

    split_xw<<<2048, 256>>>(x, Wq, Wk, Wv);
    pack_rel<<<128, 256>>>(relh, relw);
    proj_mma<<<dim3(Nv / 128, 6, Bv), 256, PJ_U32 * 4>>>(bq, bk, bv);
    attn_fused<<<dim3(8, 64), 256, SM_U32 * 4>>>(out);
}

// round 12
// speedup vs baseline: 3.3616x; 1.0237x over previous
#include <cuda_runtime.h>
#include <cuda_bf16.h>
#include <stdint.h>

constexpr int Bv = 16, Hv = 4, Dv = 64, Cv = 256, Nv = 1024;

// ---------------- static device scratch ------------------------------------
// g_PK: [bh][n][k2 0..63]  (k2 0..31 = K pairs along d, 32..63 = Q pairs)
__device__ uint32_t g_PKh[64 * 1024 * 64], g_PKl[64 * 1024 * 64];
__device__ uint32_t g_Vph[64 * 64 * 512],  g_Vpl[64 * 64 * 512];    // [bh][d][n2]
__device__ uint32_t g_Rph[4 * 1024 * 32],  g_Rpl[4 * 1024 * 32];    // [h][n][k2]
__device__ uint32_t g_xPh[16 * 128 * 1024], g_xPl[16 * 128 * 1024]; // [b][k2][n]
__device__ uint32_t g_WPh[128 * 768], g_WPl[128 * 768];             // [k2][o]

// ---------------- helpers ---------------------------------------------------
__device__ __forceinline__ uint32_t sptr(const void* p) {
    return (uint32_t)__cvta_generic_to_shared(p);
}
__device__ __forceinline__ void cp16(uint32_t d, const void* s) {
    asm volatile("cp.async.cg.shared.global [%0],[%1],16;\n" :: "r"(d), "l"(s));
}
__device__ __forceinline__ void cpcommit() { asm volatile("cp.async.commit_group;\n"); }
__device__ __forceinline__ void cpwait0()  { asm volatile("cp.async.wait_group 0;\n" ::: "memory"); }
__device__ __forceinline__ void ldm4(uint32_t* r, uint32_t a) {
    asm volatile("ldmatrix.sync.aligned.m8n8.x4.shared.b16 {%0,%1,%2,%3},[%4];\n"
                 : "=r"(r[0]), "=r"(r[1]), "=r"(r[2]), "=r"(r[3]) : "r"(a));
}
__device__ __forceinline__ uint32_t packbf(float e, float o) {
    uint32_t r;
    asm("cvt.rn.bf16x2.f32 %0, %1, %2;" : "=r"(r) : "f"(o), "f"(e));
    return r;
}
__device__ __forceinline__ void split2(float e, float o, uint32_t& h, uint32_t& l) {
    h = packbf(e, o);
    __nv_bfloat162 hb = *reinterpret_cast<__nv_bfloat162*>(&h);
    l = packbf(e - __bfloat162float(hb.x), o - __bfloat162float(hb.y));
}
__device__ __forceinline__ void mma16(float* c, const uint32_t* a, uint32_t b0, uint32_t b1) {
    asm volatile(
        "mma.sync.aligned.m16n8k16.row.col.f32.bf16.bf16.f32 "
        "{%0,%1,%2,%3},{%4,%5,%6,%7},{%8,%9},{%0,%1,%2,%3};\n"
        : "+f"(c[0]), "+f"(c[1]), "+f"(c[2]), "+f"(c[3])
        : "r"(a[0]), "r"(a[1]), "r"(a[2]), "r"(a[3]), "r"(b0), "r"(b1));
}

// ---------------------------------------------------------------------------
// Kernel 0: split x and Wcat into bf16 hi/lo pair arrays.
// ---------------------------------------------------------------------------
__global__ void split_xw(const float* __restrict__ x,
                         const float* __restrict__ Wq, const float* __restrict__ Wk,
                         const float* __restrict__ Wv) {
    const int t0 = blockIdx.x * blockDim.x + threadIdx.x;
    const int stride = gridDim.x * blockDim.x;
    for (int i = t0; i < 16 * 128 * 1024; i += stride) {
        int n = i & 1023, k2 = (i >> 10) & 127, b = i >> 17;
        const float* s = x + ((size_t)b * 256 + 2 * k2) * 1024 + n;
        uint32_t h, l;
        split2(s[0], s[1024], h, l);
        g_xPh[i] = h; g_xPl[i] = l;
    }
    for (int i = t0; i < 128 * 768; i += stride) {
        int o = i % 768, k2 = i / 768;
        int which = o >> 8, row = o & 255;
        const float* W = (which == 0) ? Wq : (which == 1) ? Wk : Wv;
        uint32_t h, l;
        split2(W[row * 256 + 2 * k2], W[row * 256 + 2 * k2 + 1], h, l);
        g_WPh[i] = h; g_WPl[i] = l;
    }
}

// ---------------------------------------------------------------------------
// Kernel 1: pack R = rel_h + rel_w, layout [h][n][k2].
// ---------------------------------------------------------------------------
__global__ void pack_rel(const float* __restrict__ relh, const float* __restrict__ relw) {
    const int t0 = blockIdx.x * blockDim.x + threadIdx.x;
    const int stride = gridDim.x * blockDim.x;
    for (int i = t0; i < 4 * 1024 * 32; i += stride) {
        int k2 = i & 31, n = (i >> 5) & 1023, hh = i >> 15;
        int d = 2 * k2;
        float e = relh[(hh * 64 + d) * 32 + (n & 31)]     + relw[(hh * 64 + d) * 32 + (n >> 5)];
        float o = relh[(hh * 64 + d + 1) * 32 + (n & 31)] + relw[(hh * 64 + d + 1) * 32 + (n >> 5)];
        uint32_t h, l;
        split2(e, o, h, l);
        g_Rph[i] = h; g_Rpl[i] = l;
    }
}

// ---------------------------------------------------------------------------
// Kernel 2: QKV projection via bf16 3-pass mma, packing epilogue.
// ---------------------------------------------------------------------------
constexpr int PJ_BUF = 17408;
constexpr int PJ_U32 = 2 * PJ_BUF;

__global__ void __launch_bounds__(256, 1)
proj_mma(const float* __restrict__ bq, const float* __restrict__ bk,
         const float* __restrict__ bv) {
    extern __shared__ uint32_t sm[];
    const int b  = blockIdx.z;
    const int o0 = blockIdx.y * 128;
    const int n0 = blockIdx.x * 128;
    const int tid = threadIdx.x, lane = tid & 31, warp = tid >> 5;
    const int g = lane >> 2, tig = lane & 3;
    const int iw = warp * 16;
    const int which = o0 >> 8;
    const int or0 = o0 & 255;

    auto stage = [&](int s, int buf) {
        int base = buf * PJ_BUF;
        #pragma unroll
        for (int it = 0; it < 8; it++) {
            int c = tid + it * 256;
            int hl = c >> 10, r = (c >> 5) & 31, ch = c & 31;
            const uint32_t* src = (hl ? g_WPl : g_WPh) + (s * 32 + r) * 768 + o0 + ch * 4;
            cp16(sptr(sm + base + hl * 4352 + r * 136 + ch * 4), src);
        }
        #pragma unroll
        for (int it = 0; it < 8; it++) {
            int c = tid + it * 256;
            int hl = c >> 10, r = (c >> 5) & 31, ch = c & 31;
            const uint32_t* src = (hl ? g_xPl : g_xPh) +
                ((size_t)(b * 128 + s * 32 + r)) * 1024 + n0 + ch * 4;
            cp16(sptr(sm + base + 8704 + hl * 4352 + r * 136 + ch * 4), src);
        }
    };
    stage(0, 0);
    cpcommit();

    float acc[16][4] = {};
    for (int s = 0; s < 4; s++) {
        cpwait0();
        __syncthreads();
        if (s < 3) { stage(s + 1, (s + 1) & 1); cpcommit(); }
        const int W0 = (s & 1) * PJ_BUF;
        const int X0 = W0 + 8704;
        #pragma unroll
        for (int kc = 0; kc < 4; kc++) {
            uint32_t Ah[4], Al[4];
            int ab = W0 + (kc * 8 + tig) * 136 + iw + g;
            Ah[0] = sm[ab];           Ah[1] = sm[ab + 8];
            Ah[2] = sm[ab + 4 * 136]; Ah[3] = sm[ab + 4 * 136 + 8];
            Al[0] = sm[ab + 4352];           Al[1] = sm[ab + 4352 + 8];
            Al[2] = sm[ab + 4352 + 4 * 136]; Al[3] = sm[ab + 4352 + 4 * 136 + 8];
            #pragma unroll
            for (int na = 0; na < 16; na++) {
                int bx = X0 + (kc * 8 + tig) * 136 + na * 8 + g;
                uint32_t b0h = sm[bx],        b1h = sm[bx + 4 * 136];
                uint32_t b0l = sm[bx + 4352], b1l = sm[bx + 4352 + 4 * 136];
                mma16(acc[na], Ah, b0h, b1h);
                mma16(acc[na], Ah, b0l, b1l);
                mma16(acc[na], Al, b0h, b1h);
            }
        }
        __syncthreads();
    }

    if (which == 2) {
        // V: pairs along n straight from adjacent accumulator cols
        #pragma unroll
        for (int na = 0; na < 16; na++) {
            int colE = n0 + na * 8 + 2 * tig;
            int ch0 = or0 + iw + g;
            float bb0 = bv[ch0], bb8 = bv[ch0 + 8];
            uint32_t h, l;
            split2(acc[na][0] + bb0, acc[na][1] + bb0, h, l);
            size_t i0v = ((size_t)(b * 4 + (ch0 >> 6)) * 64 + (ch0 & 63)) * 512 + (colE >> 1);
            g_Vph[i0v] = h; g_Vpl[i0v] = l;
            int ch1 = ch0 + 8;
            split2(acc[na][2] + bb8, acc[na][3] + bb8, h, l);
            size_t i1v = ((size_t)(b * 4 + (ch1 >> 6)) * 64 + (ch1 & 63)) * 512 + (colE >> 1);
            g_Vph[i1v] = h; g_Vpl[i1v] = l;
        }
    } else {
        // Q/K: transpose through smem, pack to g_PK [bh][n][k2]
        const float* bias = (which == 0) ? bq : bk;
        float* Of = (float*)sm;               // [128][132]
        #pragma unroll
        for (int na = 0; na < 16; na++) {
            int row0 = iw + g, col = na * 8 + 2 * tig;
            float bb0 = bias[or0 + row0], bb8 = bias[or0 + row0 + 8];
            Of[row0 * 132 + col]           = acc[na][0] + bb0;
            Of[row0 * 132 + col + 1]       = acc[na][1] + bb0;
            Of[(row0 + 8) * 132 + col]     = acc[na][2] + bb8;
            Of[(row0 + 8) * 132 + col + 1] = acc[na][3] + bb8;
        }
        __syncthreads();
        const int k2off = (which == 0) ? 32 : 0;
        #pragma unroll
        for (int it = 0; it < 32; it++) {
            int c = tid + it * 256;
            int k2l = c & 63, n = c >> 6;     // n 0..127
            float e = Of[(2 * k2l) * 132 + n];
            float o = Of[(2 * k2l + 1) * 132 + n];
            uint32_t h, l;
            split2(e, o, h, l);
            int ch = or0 + 2 * k2l;
            size_t idx = ((size_t)(b * 4 + (ch >> 6)) * 1024 + n0 + n) * 64
                         + k2off + ((ch & 63) >> 1);
            g_PKh[idx] = h; g_PKl[idx] = l;
        }
    }
}

// ---------------------------------------------------------------------------
// Kernel 3: fused flash attention, ldmatrix fragment feeds.
// smem (u32): A hi [128][68] @0, A lo @8704; B bufs @17408 (buf 8704 = hi 4352 + lo);
//             V bufs @34816 (buf 4608 = hi 2304 + lo). Total 44032 u32.
// ---------------------------------------------------------------------------
constexpr int OFF_AL = 8704;
constexpr int OFF_B  = 17408;
constexpr int BUFB   = 8704;
constexpr int OFF_V  = 34816;
constexpr int BUFV   = 4608;
constexpr int SM_U32 = 44032;             // 176128 bytes

__global__ void __launch_bounds__(256, 1)
attn_fused(float* __restrict__ out) {
    extern __shared__ uint32_t sm[];
    const int bh = blockIdx.y, h = bh & 3;
    const int i0 = blockIdx.x * 128;
    const int tid = threadIdx.x, lane = tid & 31, warp = tid >> 5;
    const int g = lane >> 2, tig = lane & 3;
    const int iw = warp * 16;
    const int quad = lane >> 3, tq = lane & 7;

    // ldmatrix per-thread bases
    const int abase = (iw + (quad & 1) * 8 + tq) * 68 + (quad >> 1) * 4;   // A/V pattern
    const int brow  = (quad >> 1) * 8 + tq;                                // B pattern
    const int bhalf = (quad & 1) * 4;
    const int vbase = ((quad & 1) * 8 + tq) * 36 + (quad >> 1) * 4;

    // ---- stage resident A = [Q;R] hi/lo (4096 chunks) ----
    #pragma unroll
    for (int it = 0; it < 16; it++) {
        int c = tid + it * 256;
        int hl = c >> 11, r = (c >> 4) & 127, ch = c & 15;
        const uint32_t* src = (ch < 8)
            ? (hl ? g_PKl : g_PKh) + ((size_t)bh * 1024 + i0 + r) * 64 + 32 + ch * 4
            : (hl ? g_Rpl : g_Rph) + ((size_t)h * 1024 + i0 + r) * 32 + (ch - 8) * 4;
        cp16(sptr(sm + (hl ? OFF_AL : 0) + r * 68 + ch * 4), src);
    }
    auto stageBV = [&](int jt, int buf) {
        #pragma unroll
        for (int it = 0; it < 8; it++) {              // B: 2048 chunks
            int c = tid + it * 256;
            int hl = c >> 10, r = (c >> 4) & 63, ch = c & 15;
            const uint32_t* src = (hl ? g_PKl : g_PKh) +
                ((size_t)bh * 1024 + jt * 64 + r) * 64 + ch * 4;
            cp16(sptr(sm + OFF_B + buf * BUFB + hl * 4352 + r * 68 + ch * 4), src);
        }
        #pragma unroll
        for (int it = 0; it < 4; it++) {              // V: 1024 chunks
            int c = tid + it * 256;
            int hl = c >> 9, r = (c >> 3) & 63, ch = c & 7;
            const uint32_t* src = (hl ? g_Vpl : g_Vph) +
                ((size_t)bh * 64 + r) * 512 + jt * 32 + ch * 4;
            cp16(sptr(sm + OFF_V + buf * BUFV + hl * 2304 + r * 36 + ch * 4), src);
        }
    };
    stageBV(0, 0);
    cpcommit();

    float m0 = -1e30f, m1 = -1e30f, s0 = 0.f, s1 = 0.f;
    float Oa[4][2][4] = {};

    for (int jt = 0; jt < 16; jt++) {
        cpwait0();
        __syncthreads();
        if (jt < 15) { stageBV(jt + 1, (jt + 1) & 1); cpcommit(); }
        const int bb = OFF_B + (jt & 1) * BUFB;
        const int vb = OFF_V + (jt & 1) * BUFV;

        // ---- S = [Q;R]^T [K;Q] over k=128 (3-pass bf16) ----
        float sacc[8][4] = {};
        #pragma unroll
        for (int kc = 0; kc < 8; kc++) {
            uint32_t Ah[4], Al[4];
            ldm4(Ah, sptr(sm + abase + kc * 8));
            ldm4(Al, sptr(sm + OFF_AL + abase + kc * 8));
            #pragma unroll
            for (int na2 = 0; na2 < 4; na2++) {
                uint32_t Bh4[4], Bl4[4];
                int bi = bb + (na2 * 16 + brow) * 68 + kc * 8 + bhalf;
                ldm4(Bh4, sptr(sm + bi));
                ldm4(Bl4, sptr(sm + bi + 4352));
                mma16(sacc[2 * na2],     Ah, Bh4[0], Bh4[1]);
                mma16(sacc[2 * na2],     Ah, Bl4[0], Bl4[1]);
                mma16(sacc[2 * na2],     Al, Bh4[0], Bh4[1]);
                mma16(sacc[2 * na2 + 1], Ah, Bh4[2], Bh4[3]);
                mma16(sacc[2 * na2 + 1], Ah, Bl4[2], Bl4[3]);
                mma16(sacc[2 * na2 + 1], Al, Bh4[2], Bh4[3]);
            }
        }

        // ---- online softmax ----
        float tm0 = -1e30f, tm1 = -1e30f;
        #pragma unroll
        for (int na = 0; na < 8; na++) {
            tm0 = fmaxf(tm0, fmaxf(sacc[na][0], sacc[na][1]));
            tm1 = fmaxf(tm1, fmaxf(sacc[na][2], sacc[na][3]));
        }
        tm0 = fmaxf(tm0, __shfl_xor_sync(0xffffffffu, tm0, 1));
        tm0 = fmaxf(tm0, __shfl_xor_sync(0xffffffffu, tm0, 2));
        tm1 = fmaxf(tm1, __shfl_xor_sync(0xffffffffu, tm1, 1));
        tm1 = fmaxf(tm1, __shfl_xor_sync(0xffffffffu, tm1, 2));
        float mn0 = fmaxf(m0, tm0), mn1 = fmaxf(m1, tm1);
        float sc0 = __expf(m0 - mn0), sc1 = __expf(m1 - mn1);
        m0 = mn0; m1 = mn1;

        float ps0 = 0.f, ps1 = 0.f;
        #pragma unroll
        for (int na = 0; na < 8; na++) {
            sacc[na][0] = __expf(sacc[na][0] - m0);
            sacc[na][1] = __expf(sacc[na][1] - m0);
            sacc[na][2] = __expf(sacc[na][2] - m1);
            sacc[na][3] = __expf(sacc[na][3] - m1);
            ps0 += sacc[na][0] + sacc[na][1];
            ps1 += sacc[na][2] + sacc[na][3];
        }
        s0 = s0 * sc0 + ps0;
        s1 = s1 * sc1 + ps1;

        float f0 = __shfl_sync(0xffffffffu, sc0, 8 * tig);
        float f1 = __shfl_sync(0xffffffffu, sc0, 8 * tig + 4);
        float q0 = __shfl_sync(0xffffffffu, sc1, 8 * tig);
        float q1 = __shfl_sync(0xffffffffu, sc1, 8 * tig + 4);
        #pragma unroll
        for (int ma = 0; ma < 4; ma++) {
            Oa[ma][0][0] *= f0; Oa[ma][0][1] *= f1; Oa[ma][0][2] *= f0; Oa[ma][0][3] *= f1;
            Oa[ma][1][0] *= q0; Oa[ma][1][1] *= q1; Oa[ma][1][2] *= q0; Oa[ma][1][3] *= q1;
        }

        // ---- O += V * P^T ----
        #pragma unroll
        for (int kc = 0; kc < 4; kc++) {
            uint32_t bh00, bl00, bh01, bl01, bh80, bl80, bh81, bl81;
            split2(sacc[2 * kc][0],     sacc[2 * kc][1],     bh00, bl00);
            split2(sacc[2 * kc + 1][0], sacc[2 * kc + 1][1], bh01, bl01);
            split2(sacc[2 * kc][2],     sacc[2 * kc][3],     bh80, bl80);
            split2(sacc[2 * kc + 1][2], sacc[2 * kc + 1][3], bh81, bl81);
            #pragma unroll
            for (int ma = 0; ma < 4; ma++) {
                uint32_t Vh[4], Vl[4];
                int vi = vb + ma * 16 * 36 + vbase + kc * 8;
                ldm4(Vh, sptr(sm + vi));
                ldm4(Vl, sptr(sm + vi + 2304));
                mma16(Oa[ma][0], Vh, bh00, bh01);
                mma16(Oa[ma][0], Vh, bl00, bl01);
                mma16(Oa[ma][0], Vl, bh00, bh01);
                mma16(Oa[ma][1], Vh, bh80, bh81);
                mma16(Oa[ma][1], Vh, bl80, bl81);
                mma16(Oa[ma][1], Vl, bh80, bh81);
            }
        }
    }

    // ---- epilogue ----
    s0 += __shfl_xor_sync(0xffffffffu, s0, 1);
    s0 += __shfl_xor_sync(0xffffffffu, s0, 2);
    s1 += __shfl_xor_sync(0xffffffffu, s1, 1);
    s1 += __shfl_xor_sync(0xffffffffu, s1, 2);
    float i00 = 1.f / __shfl_sync(0xffffffffu, s0, 8 * tig);
    float i01 = 1.f / __shfl_sync(0xffffffffu, s0, 8 * tig + 4);
    float i10 = 1.f / __shfl_sync(0xffffffffu, s1, 8 * tig);
    float i11 = 1.f / __shfl_sync(0xffffffffu, s1, 8 * tig + 4);

    __syncthreads();
    float* Of = (float*)(sm + OFF_B);     // [64 d][132]
    #pragma unroll
    for (int ma = 0; ma < 4; ma++) {
        int d0 = ma * 16 + g;
        #pragma unroll
        for (int ni = 0; ni < 2; ni++) {
            float ie = ni ? i10 : i00, io = ni ? i11 : i01;
            int col = iw + ni * 8 + 2 * tig;
            Of[d0 * 132 + col]           = Oa[ma][ni][0] * ie;
            Of[d0 * 132 + col + 1]       = Oa[ma][ni][1] * io;
            Of[(d0 + 8) * 132 + col]     = Oa[ma][ni][2] * ie;
            Of[(d0 + 8) * 132 + col + 1] = Oa[ma][ni][3] * io;
        }
    }
    __syncthreads();
    #pragma unroll
    for (int it = 0; it < 8; it++) {
        int c = tid + it * 256;
        int row = c >> 5, col4 = c & 31;
        float4 v = *(float4*)(Of + row * 132 + col4 * 4);
        *(float4*)(out + ((size_t)bh * 64 + row) * 1024 + i0 + col4 * 4) = v;
    }
}

// ---------------------------------------------------------------------------
extern "C" void kernel_launch(void* const* d_in, const int* in_sizes, int n_in,
                              void* d_out, int out_size) {
    const float* x    = (const float*)d_in[0];
    const float* Wq   = (const float*)d_in[1];
    const float* bq   = (const float*)d_in[2];
    const float* Wk   = (const float*)d_in[3];
    const float* bk   = (const float*)d_in[4];
    const float* Wv   = (const float*)d_in[5];
    const float* bv   = (const float*)d_in[6];
    const float* relh = (const float*)d_in[7];
    const float* relw = (const float*)d_in[8];
    float* out = (float*)d_out;

    cudaFuncSetAttribute(proj_mma, cudaFuncAttributeMaxDynamicSharedMemorySize,
                         PJ_U32 * 4);
    cudaFuncSetAttribute(attn_fused, cudaFuncAttributeMaxDynamicSharedMemorySize,
                         SM_U32 * 4);

    split_xw<<<2048, 256>>>(x, Wq, Wk, Wv);
    pack_rel<<<128, 256>>>(relh, relw);
    proj_mma<<<dim3(Nv / 128, 6, Bv), 256, PJ_U32 * 4>>>(bq, bk, bv);
    attn_fused<<<dim3(8, 64), 256, SM_U32 * 4>>>(out);
}

// round 14
// speedup vs baseline: 3.3682x; 1.0020x over previous
#include <cuda_runtime.h>
#include <cuda_bf16.h>
#include <stdint.h>

constexpr int Bv = 16, Hv = 4, Dv = 64, Cv = 256, Nv = 1024;

// ---------------- static device scratch ------------------------------------
// g_PK: [bh][n][k2 0..63]  (k2 0..31 = K pairs along d, 32..63 = Q pairs)
__device__ uint32_t g_PKh[64 * 1024 * 64], g_PKl[64 * 1024 * 64];
__device__ uint32_t g_Vph[64 * 64 * 512],  g_Vpl[64 * 64 * 512];    // [bh][d][n2]
__device__ uint32_t g_Rph[4 * 1024 * 32],  g_Rpl[4 * 1024 * 32];    // [h][n][k2]
__device__ uint32_t g_xPh[16 * 128 * 1024], g_xPl[16 * 128 * 1024]; // [b][k2][n]
__device__ uint32_t g_WPh[128 * 768], g_WPl[128 * 768];             // [k2][o]

// ---------------- helpers ---------------------------------------------------
__device__ __forceinline__ uint32_t sptr(const void* p) {
    return (uint32_t)__cvta_generic_to_shared(p);
}
__device__ __forceinline__ void cp16(uint32_t d, const void* s) {
    asm volatile("cp.async.cg.shared.global [%0],[%1],16;\n" :: "r"(d), "l"(s));
}
__device__ __forceinline__ void cpcommit() { asm volatile("cp.async.commit_group;\n"); }
__device__ __forceinline__ void cpwait0()  { asm volatile("cp.async.wait_group 0;\n" ::: "memory"); }
__device__ __forceinline__ void ldm4(uint32_t* r, uint32_t a) {
    asm volatile("ldmatrix.sync.aligned.m8n8.x4.shared.b16 {%0,%1,%2,%3},[%4];\n"
                 : "=r"(r[0]), "=r"(r[1]), "=r"(r[2]), "=r"(r[3]) : "r"(a));
}
__device__ __forceinline__ uint32_t packbf(float e, float o) {
    uint32_t r;
    asm("cvt.rn.bf16x2.f32 %0, %1, %2;" : "=r"(r) : "f"(o), "f"(e));
    return r;
}
__device__ __forceinline__ void split2(float e, float o, uint32_t& h, uint32_t& l) {
    h = packbf(e, o);
    __nv_bfloat162 hb = *reinterpret_cast<__nv_bfloat162*>(&h);
    l = packbf(e - __bfloat162float(hb.x), o - __bfloat162float(hb.y));
}
__device__ __forceinline__ void mma16(float* c, const uint32_t* a, uint32_t b0, uint32_t b1) {
    asm volatile(
        "mma.sync.aligned.m16n8k16.row.col.f32.bf16.bf16.f32 "
        "{%0,%1,%2,%3},{%4,%5,%6,%7},{%8,%9},{%0,%1,%2,%3};\n"
        : "+f"(c[0]), "+f"(c[1]), "+f"(c[2]), "+f"(c[3])
        : "r"(a[0]), "r"(a[1]), "r"(a[2]), "r"(a[3]), "r"(b0), "r"(b1));
}

// ---------------------------------------------------------------------------
// Kernel 0: split x and Wcat into bf16 hi/lo pair arrays.
// ---------------------------------------------------------------------------
__global__ void split_xw(const float* __restrict__ x,
                         const float* __restrict__ Wq, const float* __restrict__ Wk,
                         const float* __restrict__ Wv) {
    const int t0 = blockIdx.x * blockDim.x + threadIdx.x;
    const int stride = gridDim.x * blockDim.x;
    for (int i = t0; i < 16 * 128 * 1024; i += stride) {
        int n = i & 1023, k2 = (i >> 10) & 127, b = i >> 17;
        const float* s = x + ((size_t)b * 256 + 2 * k2) * 1024 + n;
        uint32_t h, l;
        split2(s[0], s[1024], h, l);
        g_xPh[i] = h; g_xPl[i] = l;
    }
    for (int i = t0; i < 128 * 768; i += stride) {
        int o = i % 768, k2 = i / 768;
        int which = o >> 8, row = o & 255;
        const float* W = (which == 0) ? Wq : (which == 1) ? Wk : Wv;
        uint32_t h, l;
        split2(W[row * 256 + 2 * k2], W[row * 256 + 2 * k2 + 1], h, l);
        g_WPh[i] = h; g_WPl[i] = l;
    }
}

// ---------------------------------------------------------------------------
// Kernel 1: pack R = rel_h + rel_w, layout [h][n][k2].
// ---------------------------------------------------------------------------
__global__ void pack_rel(const float* __restrict__ relh, const float* __restrict__ relw) {
    const int t0 = blockIdx.x * blockDim.x + threadIdx.x;
    const int stride = gridDim.x * blockDim.x;
    for (int i = t0; i < 4 * 1024 * 32; i += stride) {
        int k2 = i & 31, n = (i >> 5) & 1023, hh = i >> 15;
        int d = 2 * k2;
        float e = relh[(hh * 64 + d) * 32 + (n & 31)]     + relw[(hh * 64 + d) * 32 + (n >> 5)];
        float o = relh[(hh * 64 + d + 1) * 32 + (n & 31)] + relw[(hh * 64 + d + 1) * 32 + (n >> 5)];
        uint32_t h, l;
        split2(e, o, h, l);
        g_Rph[i] = h; g_Rpl[i] = l;
    }
}

// ---------------------------------------------------------------------------
// Kernel 2: QKV projection via bf16 3-pass mma, packing epilogue.
// Pass-reordered mma (groups of 4 accumulators, distance 4).
// ---------------------------------------------------------------------------
constexpr int PJ_BUF = 17408;
constexpr int PJ_U32 = 2 * PJ_BUF;

__global__ void __launch_bounds__(256, 1)
proj_mma(const float* __restrict__ bq, const float* __restrict__ bk,
         const float* __restrict__ bv) {
    extern __shared__ uint32_t sm[];
    const int b  = blockIdx.z;
    const int o0 = blockIdx.y * 128;
    const int n0 = blockIdx.x * 128;
    const int tid = threadIdx.x, lane = tid & 31, warp = tid >> 5;
    const int g = lane >> 2, tig = lane & 3;
    const int iw = warp * 16;
    const int which = o0 >> 8;
    const int or0 = o0 & 255;

    auto stage = [&](int s, int buf) {
        int base = buf * PJ_BUF;
        #pragma unroll
        for (int it = 0; it < 8; it++) {
            int c = tid + it * 256;
            int hl = c >> 10, r = (c >> 5) & 31, ch = c & 31;
            const uint32_t* src = (hl ? g_WPl : g_WPh) + (s * 32 + r) * 768 + o0 + ch * 4;
            cp16(sptr(sm + base + hl * 4352 + r * 136 + ch * 4), src);
        }
        #pragma unroll
        for (int it = 0; it < 8; it++) {
            int c = tid + it * 256;
            int hl = c >> 10, r = (c >> 5) & 31, ch = c & 31;
            const uint32_t* src = (hl ? g_xPl : g_xPh) +
                ((size_t)(b * 128 + s * 32 + r)) * 1024 + n0 + ch * 4;
            cp16(sptr(sm + base + 8704 + hl * 4352 + r * 136 + ch * 4), src);
        }
    };
    stage(0, 0);
    cpcommit();

    float acc[16][4] = {};
    for (int s = 0; s < 4; s++) {
        cpwait0();
        __syncthreads();
        if (s < 3) { stage(s + 1, (s + 1) & 1); cpcommit(); }
        const int W0 = (s & 1) * PJ_BUF;
        const int X0 = W0 + 8704;
        #pragma unroll
        for (int kc = 0; kc < 4; kc++) {
            uint32_t Ah[4], Al[4];
            int ab = W0 + (kc * 8 + tig) * 136 + iw + g;
            Ah[0] = sm[ab];           Ah[1] = sm[ab + 8];
            Ah[2] = sm[ab + 4 * 136]; Ah[3] = sm[ab + 4 * 136 + 8];
            Al[0] = sm[ab + 4352];           Al[1] = sm[ab + 4352 + 8];
            Al[2] = sm[ab + 4352 + 4 * 136]; Al[3] = sm[ab + 4352 + 4 * 136 + 8];
            #pragma unroll
            for (int nb = 0; nb < 4; nb++) {
                uint32_t b0h[4], b1h[4], b0l[4], b1l[4];
                #pragma unroll
                for (int j = 0; j < 4; j++) {
                    int bx = X0 + (kc * 8 + tig) * 136 + (nb * 4 + j) * 8 + g;
                    b0h[j] = sm[bx];        b1h[j] = sm[bx + 4 * 136];
                    b0l[j] = sm[bx + 4352]; b1l[j] = sm[bx + 4352 + 4 * 136];
                }
                #pragma unroll
                for (int j = 0; j < 4; j++) mma16(acc[nb * 4 + j], Ah, b0h[j], b1h[j]);
                #pragma unroll
                for (int j = 0; j < 4; j++) mma16(acc[nb * 4 + j], Ah, b0l[j], b1l[j]);
                #pragma unroll
                for (int j = 0; j < 4; j++) mma16(acc[nb * 4 + j], Al, b0h[j], b1h[j]);
            }
        }
        __syncthreads();
    }

    if (which == 2) {
        // V: pairs along n straight from adjacent accumulator cols
        #pragma unroll
        for (int na = 0; na < 16; na++) {
            int colE = n0 + na * 8 + 2 * tig;
            int ch0 = or0 + iw + g;
            float bb0 = bv[ch0], bb8 = bv[ch0 + 8];
            uint32_t h, l;
            split2(acc[na][0] + bb0, acc[na][1] + bb0, h, l);
            size_t i0v = ((size_t)(b * 4 + (ch0 >> 6)) * 64 + (ch0 & 63)) * 512 + (colE >> 1);
            g_Vph[i0v] = h; g_Vpl[i0v] = l;
            int ch1 = ch0 + 8;
            split2(acc[na][2] + bb8, acc[na][3] + bb8, h, l);
            size_t i1v = ((size_t)(b * 4 + (ch1 >> 6)) * 64 + (ch1 & 63)) * 512 + (colE >> 1);
            g_Vph[i1v] = h; g_Vpl[i1v] = l;
        }
    } else {
        // Q/K: transpose through smem, pack to g_PK [bh][n][k2]
        const float* bias = (which == 0) ? bq : bk;
        float* Of = (float*)sm;               // [128][132]
        #pragma unroll
        for (int na = 0; na < 16; na++) {
            int row0 = iw + g, col = na * 8 + 2 * tig;
            float bb0 = bias[or0 + row0], bb8 = bias[or0 + row0 + 8];
            Of[row0 * 132 + col]           = acc[na][0] + bb0;
            Of[row0 * 132 + col + 1]       = acc[na][1] + bb0;
            Of[(row0 + 8) * 132 + col]     = acc[na][2] + bb8;
            Of[(row0 + 8) * 132 + col + 1] = acc[na][3] + bb8;
        }
        __syncthreads();
        const int k2off = (which == 0) ? 32 : 0;
        #pragma unroll
        for (int it = 0; it < 32; it++) {
            int c = tid + it * 256;
            int k2l = c & 63, n = c >> 6;     // n 0..127
            float e = Of[(2 * k2l) * 132 + n];
            float o = Of[(2 * k2l + 1) * 132 + n];
            uint32_t h, l;
            split2(e, o, h, l);
            int ch = or0 + 2 * k2l;
            size_t idx = ((size_t)(b * 4 + (ch >> 6)) * 1024 + n0 + n) * 64
                         + k2off + ((ch & 63) >> 1);
            g_PKh[idx] = h; g_PKl[idx] = l;
        }
    }
}

// ---------------------------------------------------------------------------
// Kernel 3: fused flash attention, ldmatrix feeds, pass-reordered mma.
// ---------------------------------------------------------------------------
constexpr int OFF_AL = 8704;
constexpr int OFF_B  = 17408;
constexpr int BUFB   = 8704;
constexpr int OFF_V  = 34816;
constexpr int BUFV   = 4608;
constexpr int SM_U32 = 44032;             // 176128 bytes

__global__ void __launch_bounds__(256, 1)
attn_fused(float* __restrict__ out) {
    extern __shared__ uint32_t sm[];
    const int bh = blockIdx.y, h = bh & 3;
    const int i0 = blockIdx.x * 128;
    const int tid = threadIdx.x, lane = tid & 31, warp = tid >> 5;
    const int g = lane >> 2, tig = lane & 3;
    const int iw = warp * 16;
    const int quad = lane >> 3, tq = lane & 7;

    const int abase = (iw + (quad & 1) * 8 + tq) * 68 + (quad >> 1) * 4;
    const int brow  = (quad >> 1) * 8 + tq;
    const int bhalf = (quad & 1) * 4;
    const int vbase = ((quad & 1) * 8 + tq) * 36 + (quad >> 1) * 4;

    #pragma unroll
    for (int it = 0; it < 16; it++) {
        int c = tid + it * 256;
        int hl = c >> 11, r = (c >> 4) & 127, ch = c & 15;
        const uint32_t* src = (ch < 8)
            ? (hl ? g_PKl : g_PKh) + ((size_t)bh * 1024 + i0 + r) * 64 + 32 + ch * 4
            : (hl ? g_Rpl : g_Rph) + ((size_t)h * 1024 + i0 + r) * 32 + (ch - 8) * 4;
        cp16(sptr(sm + (hl ? OFF_AL : 0) + r * 68 + ch * 4), src);
    }
    auto stageBV = [&](int jt, int buf) {
        #pragma unroll
        for (int it = 0; it < 8; it++) {
            int c = tid + it * 256;
            int hl = c >> 10, r = (c >> 4) & 63, ch = c & 15;
            const uint32_t* src = (hl ? g_PKl : g_PKh) +
                ((size_t)bh * 1024 + jt * 64 + r) * 64 + ch * 4;
            cp16(sptr(sm + OFF_B + buf * BUFB + hl * 4352 + r * 68 + ch * 4), src);
        }
        #pragma unroll
        for (int it = 0; it < 4; it++) {
            int c = tid + it * 256;
            int hl = c >> 9, r = (c >> 3) & 63, ch = c & 7;
            const uint32_t* src = (hl ? g_Vpl : g_Vph) +
                ((size_t)bh * 64 + r) * 512 + jt * 32 + ch * 4;
            cp16(sptr(sm + OFF_V + buf * BUFV + hl * 2304 + r * 36 + ch * 4), src);
        }
    };
    stageBV(0, 0);
    cpcommit();

    float m0 = -1e30f, m1 = -1e30f, s0 = 0.f, s1 = 0.f;
    float Oa[4][2][4] = {};

    for (int jt = 0; jt < 16; jt++) {
        cpwait0();
        __syncthreads();
        if (jt < 15) { stageBV(jt + 1, (jt + 1) & 1); cpcommit(); }
        const int bb = OFF_B + (jt & 1) * BUFB;
        const int vb = OFF_V + (jt & 1) * BUFV;

        // ---- S: load all fragments for k-chunk, pass-ordered mma (dist 8) ----
        float sacc[8][4] = {};
        #pragma unroll
        for (int kc = 0; kc < 8; kc++) {
            uint32_t Ah[4], Al[4];
            ldm4(Ah, sptr(sm + abase + kc * 8));
            ldm4(Al, sptr(sm + OFF_AL + abase + kc * 8));
            uint32_t Bh4[4][4], Bl4[4][4];
            #pragma unroll
            for (int na2 = 0; na2 < 4; na2++) {
                int bi = bb + (na2 * 16 + brow) * 68 + kc * 8 + bhalf;
                ldm4(Bh4[na2], sptr(sm + bi));
                ldm4(Bl4[na2], sptr(sm + bi + 4352));
            }
            #pragma unroll
            for (int na2 = 0; na2 < 4; na2++) {
                mma16(sacc[2 * na2],     Ah, Bh4[na2][0], Bh4[na2][1]);
                mma16(sacc[2 * na2 + 1], Ah, Bh4[na2][2], Bh4[na2][3]);
            }
            #pragma unroll
            for (int na2 = 0; na2 < 4; na2++) {
                mma16(sacc[2 * na2],     Ah, Bl4[na2][0], Bl4[na2][1]);
                mma16(sacc[2 * na2 + 1], Ah, Bl4[na2][2], Bl4[na2][3]);
            }
            #pragma unroll
            for (int na2 = 0; na2 < 4; na2++) {
                mma16(sacc[2 * na2],     Al, Bh4[na2][0], Bh4[na2][1]);
                mma16(sacc[2 * na2 + 1], Al, Bh4[na2][2], Bh4[na2][3]);
            }
        }

        // ---- online softmax ----
        float tm0 = -1e30f, tm1 = -1e30f;
        #pragma unroll
        for (int na = 0; na < 8; na++) {
            tm0 = fmaxf(tm0, fmaxf(sacc[na][0], sacc[na][1]));
            tm1 = fmaxf(tm1, fmaxf(sacc[na][2], sacc[na][3]));
        }
        tm0 = fmaxf(tm0, __shfl_xor_sync(0xffffffffu, tm0, 1));
        tm0 = fmaxf(tm0, __shfl_xor_sync(0xffffffffu, tm0, 2));
        tm1 = fmaxf(tm1, __shfl_xor_sync(0xffffffffu, tm1, 1));
        tm1 = fmaxf(tm1, __shfl_xor_sync(0xffffffffu, tm1, 2));
        float mn0 = fmaxf(m0, tm0), mn1 = fmaxf(m1, tm1);
        float sc0 = __expf(m0 - mn0), sc1 = __expf(m1 - mn1);
        m0 = mn0; m1 = mn1;

        float ps0 = 0.f, ps1 = 0.f;
        #pragma unroll
        for (int na = 0; na < 8; na++) {
            sacc[na][0] = __expf(sacc[na][0] - m0);
            sacc[na][1] = __expf(sacc[na][1] - m0);
            sacc[na][2] = __expf(sacc[na][2] - m1);
            sacc[na][3] = __expf(sacc[na][3] - m1);
            ps0 += sacc[na][0] + sacc[na][1];
            ps1 += sacc[na][2] + sacc[na][3];
        }
        s0 = s0 * sc0 + ps0;
        s1 = s1 * sc1 + ps1;

        float f0 = __shfl_sync(0xffffffffu, sc0, 8 * tig);
        float f1 = __shfl_sync(0xffffffffu, sc0, 8 * tig + 4);
        float q0 = __shfl_sync(0xffffffffu, sc1, 8 * tig);
        float q1 = __shfl_sync(0xffffffffu, sc1, 8 * tig + 4);
        #pragma unroll
        for (int ma = 0; ma < 4; ma++) {
            Oa[ma][0][0] *= f0; Oa[ma][0][1] *= f1; Oa[ma][0][2] *= f0; Oa[ma][0][3] *= f1;
            Oa[ma][1][0] *= q0; Oa[ma][1][1] *= q1; Oa[ma][1][2] *= q0; Oa[ma][1][3] *= q1;
        }

        // ---- PV: all V fragments up front, pass-ordered (dist 8) ----
        #pragma unroll
        for (int kc = 0; kc < 4; kc++) {
            uint32_t bh00, bl00, bh01, bl01, bh80, bl80, bh81, bl81;
            split2(sacc[2 * kc][0],     sacc[2 * kc][1],     bh00, bl00);
            split2(sacc[2 * kc + 1][0], sacc[2 * kc + 1][1], bh01, bl01);
            split2(sacc[2 * kc][2],     sacc[2 * kc][3],     bh80, bl80);
            split2(sacc[2 * kc + 1][2], sacc[2 * kc + 1][3], bh81, bl81);
            uint32_t Vh4[4][4], Vl4[4][4];
            #pragma unroll
            for (int ma = 0; ma < 4; ma++) {
                int vi = vb + ma * 16 * 36 + vbase + kc * 8;
                ldm4(Vh4[ma], sptr(sm + vi));
                ldm4(Vl4[ma], sptr(sm + vi + 2304));
            }
            #pragma unroll
            for (int ma = 0; ma < 4; ma++) {
                mma16(Oa[ma][0], Vh4[ma], bh00, bh01);
                mma16(Oa[ma][1], Vh4[ma], bh80, bh81);
            }
            #pragma unroll
            for (int ma = 0; ma < 4; ma++) {
                mma16(Oa[ma][0], Vh4[ma], bl00, bl01);
                mma16(Oa[ma][1], Vh4[ma], bl80, bl81);
            }
            #pragma unroll
            for (int ma = 0; ma < 4; ma++) {
                mma16(Oa[ma][0], Vl4[ma], bh00, bh01);
                mma16(Oa[ma][1], Vl4[ma], bh80, bh81);
            }
        }
    }

    // ---- epilogue ----
    s0 += __shfl_xor_sync(0xffffffffu, s0, 1);
    s0 += __shfl_xor_sync(0xffffffffu, s0, 2);
    s1 += __shfl_xor_sync(0xffffffffu, s1, 1);
    s1 += __shfl_xor_sync(0xffffffffu, s1, 2);
    float i00 = 1.f / __shfl_sync(0xffffffffu, s0, 8 * tig);
    float i01 = 1.f / __shfl_sync(0xffffffffu, s0, 8 * tig + 4);
    float i10 = 1.f / __shfl_sync(0xffffffffu, s1, 8 * tig);
    float i11 = 1.f / __shfl_sync(0xffffffffu, s1, 8 * tig + 4);

    __syncthreads();
    float* Of = (float*)(sm + OFF_B);     // [64 d][132]
    #pragma unroll
    for (int ma = 0; ma < 4; ma++) {
        int d0 = ma * 16 + g;
        #pragma unroll
        for (int ni = 0; ni < 2; ni++) {
            float ie = ni ? i10 : i00, io = ni ? i11 : i01;
            int col = iw + ni * 8 + 2 * tig;
            Of[d0 * 132 + col]           = Oa[ma][ni][0] * ie;
            Of[d0 * 132 + col + 1]       = Oa[ma][ni][1] * io;
            Of[(d0 + 8) * 132 + col]     = Oa[ma][ni][2] * ie;
            Of[(d0 + 8) * 132 + col + 1] = Oa[ma][ni][3] * io;
        }
    }
    __syncthreads();
    #pragma unroll
    for (int it = 0; it < 8; it++) {
        int c = tid + it * 256;
        int row = c >> 5, col4 = c & 31;
        float4 v = *(float4*)(Of + row * 132 + col4 * 4);
        *(float4*)(out + ((size_t)bh * 64 + row) * 1024 + i0 + col4 * 4) = v;
    }
}

// ---------------------------------------------------------------------------
extern "C" void kernel_launch(void* const* d_in, const int* in_sizes, int n_in,
                              void* d_out, int out_size) {
    const float* x    = (const float*)d_in[0];
    const float* Wq   = (const float*)d_in[1];
    const float* bq   = (const float*)d_in[2];
    const float* Wk   = (const float*)d_in[3];
    const float* bk   = (const float*)d_in[4];
    const float* Wv   = (const float*)d_in[5];
    const float* bv   = (const float*)d_in[6];
    const float* relh = (const float*)d_in[7];
    const float* relw = (const float*)d_in[8];
    float* out = (float*)d_out;

    cudaFuncSetAttribute(proj_mma, cudaFuncAttributeMaxDynamicSharedMemorySize,
                         PJ_U32 * 4);
    cudaFuncSetAttribute(attn_fused, cudaFuncAttributeMaxDynamicSharedMemorySize,
                         SM_U32 * 4);

    split_xw<<<2048, 256>>>(x, Wq, Wk, Wv);
    pack_rel<<<128, 256>>>(relh, relw);
    proj_mma<<<dim3(Nv / 128, 6, Bv), 256, PJ_U32 * 4>>>(bq, bk, bv);
    attn_fused<<<dim3(8, 64), 256, SM_U32 * 4>>>(out);
}

// round 15
// speedup vs baseline: 4.0043x; 1.1889x over previous
#include <cuda_runtime.h>
#include <cuda_bf16.h>
#include <stdint.h>

constexpr int Bv = 16, Hv = 4, Dv = 64, Cv = 256, Nv = 1024;

// ---------------- static device scratch ------------------------------------
// g_PK: [bh][n][k2 0..63]  (k2 0..31 = K pairs along d, 32..63 = Q pairs)
__device__ uint32_t g_PKh[64 * 1024 * 64], g_PKl[64 * 1024 * 64];
__device__ uint32_t g_Vp[64 * 64 * 512];                            // [bh][d][n2] fp16x2
__device__ uint32_t g_Rph[4 * 1024 * 32],  g_Rpl[4 * 1024 * 32];    // [h][n][k2]
__device__ uint32_t g_xPh[16 * 128 * 1024], g_xPl[16 * 128 * 1024]; // [b][k2][n]
__device__ uint32_t g_WPh[128 * 768], g_WPl[128 * 768];             // [k2][o]

// ---------------- helpers ---------------------------------------------------
__device__ __forceinline__ uint32_t sptr(const void* p) {
    return (uint32_t)__cvta_generic_to_shared(p);
}
__device__ __forceinline__ void cp16(uint32_t d, const void* s) {
    asm volatile("cp.async.cg.shared.global [%0],[%1],16;\n" :: "r"(d), "l"(s));
}
__device__ __forceinline__ void cpcommit() { asm volatile("cp.async.commit_group;\n"); }
__device__ __forceinline__ void cpwait0()  { asm volatile("cp.async.wait_group 0;\n" ::: "memory"); }
__device__ __forceinline__ void ldm4(uint32_t* r, uint32_t a) {
    asm volatile("ldmatrix.sync.aligned.m8n8.x4.shared.b16 {%0,%1,%2,%3},[%4];\n"
                 : "=r"(r[0]), "=r"(r[1]), "=r"(r[2]), "=r"(r[3]) : "r"(a));
}
__device__ __forceinline__ uint32_t packbf(float e, float o) {
    uint32_t r;
    asm("cvt.rn.bf16x2.f32 %0, %1, %2;" : "=r"(r) : "f"(o), "f"(e));
    return r;
}
__device__ __forceinline__ uint32_t packhf(float e, float o) {   // fp16x2, even in LOW
    uint32_t r;
    asm("cvt.rn.f16x2.f32 %0, %1, %2;" : "=r"(r) : "f"(o), "f"(e));
    return r;
}
__device__ __forceinline__ void split2(float e, float o, uint32_t& h, uint32_t& l) {
    h = packbf(e, o);
    __nv_bfloat162 hb = *reinterpret_cast<__nv_bfloat162*>(&h);
    l = packbf(e - __bfloat162float(hb.x), o - __bfloat162float(hb.y));
}
__device__ __forceinline__ void mma16(float* c, const uint32_t* a, uint32_t b0, uint32_t b1) {
    asm volatile(
        "mma.sync.aligned.m16n8k16.row.col.f32.bf16.bf16.f32 "
        "{%0,%1,%2,%3},{%4,%5,%6,%7},{%8,%9},{%0,%1,%2,%3};\n"
        : "+f"(c[0]), "+f"(c[1]), "+f"(c[2]), "+f"(c[3])
        : "r"(a[0]), "r"(a[1]), "r"(a[2]), "r"(a[3]), "r"(b0), "r"(b1));
}
__device__ __forceinline__ void mma16h(float* c, const uint32_t* a, uint32_t b0, uint32_t b1) {
    asm volatile(
        "mma.sync.aligned.m16n8k16.row.col.f32.f16.f16.f32 "
        "{%0,%1,%2,%3},{%4,%5,%6,%7},{%8,%9},{%0,%1,%2,%3};\n"
        : "+f"(c[0]), "+f"(c[1]), "+f"(c[2]), "+f"(c[3])
        : "r"(a[0]), "r"(a[1]), "r"(a[2]), "r"(a[3]), "r"(b0), "r"(b1));
}

// ---------------------------------------------------------------------------
// Kernel 0: split x and Wcat into bf16 hi/lo pair arrays.
// ---------------------------------------------------------------------------
__global__ void split_xw(const float* __restrict__ x,
                         const float* __restrict__ Wq, const float* __restrict__ Wk,
                         const float* __restrict__ Wv) {
    const int t0 = blockIdx.x * blockDim.x + threadIdx.x;
    const int stride = gridDim.x * blockDim.x;
    for (int i = t0; i < 16 * 128 * 1024; i += stride) {
        int n = i & 1023, k2 = (i >> 10) & 127, b = i >> 17;
        const float* s = x + ((size_t)b * 256 + 2 * k2) * 1024 + n;
        uint32_t h, l;
        split2(s[0], s[1024], h, l);
        g_xPh[i] = h; g_xPl[i] = l;
    }
    for (int i = t0; i < 128 * 768; i += stride) {
        int o = i % 768, k2 = i / 768;
        int which = o >> 8, row = o & 255;
        const float* W = (which == 0) ? Wq : (which == 1) ? Wk : Wv;
        uint32_t h, l;
        split2(W[row * 256 + 2 * k2], W[row * 256 + 2 * k2 + 1], h, l);
        g_WPh[i] = h; g_WPl[i] = l;
    }
}

// ---------------------------------------------------------------------------
// Kernel 1: pack R = rel_h + rel_w, layout [h][n][k2].
// ---------------------------------------------------------------------------
__global__ void pack_rel(const float* __restrict__ relh, const float* __restrict__ relw) {
    const int t0 = blockIdx.x * blockDim.x + threadIdx.x;
    const int stride = gridDim.x * blockDim.x;
    for (int i = t0; i < 4 * 1024 * 32; i += stride) {
        int k2 = i & 31, n = (i >> 5) & 1023, hh = i >> 15;
        int d = 2 * k2;
        float e = relh[(hh * 64 + d) * 32 + (n & 31)]     + relw[(hh * 64 + d) * 32 + (n >> 5)];
        float o = relh[(hh * 64 + d + 1) * 32 + (n & 31)] + relw[(hh * 64 + d + 1) * 32 + (n >> 5)];
        uint32_t h, l;
        split2(e, o, h, l);
        g_Rph[i] = h; g_Rpl[i] = l;
    }
}

// ---------------------------------------------------------------------------
// Kernel 2: QKV projection via bf16 3-pass mma, packing epilogue.
// ---------------------------------------------------------------------------
constexpr int PJ_BUF = 17408;
constexpr int PJ_U32 = 2 * PJ_BUF;

__global__ void __launch_bounds__(256, 1)
proj_mma(const float* __restrict__ bq, const float* __restrict__ bk,
         const float* __restrict__ bv) {
    extern __shared__ uint32_t sm[];
    const int b  = blockIdx.z;
    const int o0 = blockIdx.y * 128;
    const int n0 = blockIdx.x * 128;
    const int tid = threadIdx.x, lane = tid & 31, warp = tid >> 5;
    const int g = lane >> 2, tig = lane & 3;
    const int iw = warp * 16;
    const int which = o0 >> 8;
    const int or0 = o0 & 255;

    auto stage = [&](int s, int buf) {
        int base = buf * PJ_BUF;
        #pragma unroll
        for (int it = 0; it < 8; it++) {
            int c = tid + it * 256;
            int hl = c >> 10, r = (c >> 5) & 31, ch = c & 31;
            const uint32_t* src = (hl ? g_WPl : g_WPh) + (s * 32 + r) * 768 + o0 + ch * 4;
            cp16(sptr(sm + base + hl * 4352 + r * 136 + ch * 4), src);
        }
        #pragma unroll
        for (int it = 0; it < 8; it++) {
            int c = tid + it * 256;
            int hl = c >> 10, r = (c >> 5) & 31, ch = c & 31;
            const uint32_t* src = (hl ? g_xPl : g_xPh) +
                ((size_t)(b * 128 + s * 32 + r)) * 1024 + n0 + ch * 4;
            cp16(sptr(sm + base + 8704 + hl * 4352 + r * 136 + ch * 4), src);
        }
    };
    stage(0, 0);
    cpcommit();

    float acc[16][4] = {};
    for (int s = 0; s < 4; s++) {
        cpwait0();
        __syncthreads();
        if (s < 3) { stage(s + 1, (s + 1) & 1); cpcommit(); }
        const int W0 = (s & 1) * PJ_BUF;
        const int X0 = W0 + 8704;
        #pragma unroll
        for (int kc = 0; kc < 4; kc++) {
            uint32_t Ah[4], Al[4];
            int ab = W0 + (kc * 8 + tig) * 136 + iw + g;
            Ah[0] = sm[ab];           Ah[1] = sm[ab + 8];
            Ah[2] = sm[ab + 4 * 136]; Ah[3] = sm[ab + 4 * 136 + 8];
            Al[0] = sm[ab + 4352];           Al[1] = sm[ab + 4352 + 8];
            Al[2] = sm[ab + 4352 + 4 * 136]; Al[3] = sm[ab + 4352 + 4 * 136 + 8];
            #pragma unroll
            for (int nb = 0; nb < 4; nb++) {
                uint32_t b0h[4], b1h[4], b0l[4], b1l[4];
                #pragma unroll
                for (int j = 0; j < 4; j++) {
                    int bx = X0 + (kc * 8 + tig) * 136 + (nb * 4 + j) * 8 + g;
                    b0h[j] = sm[bx];        b1h[j] = sm[bx + 4 * 136];
                    b0l[j] = sm[bx + 4352]; b1l[j] = sm[bx + 4352 + 4 * 136];
                }
                #pragma unroll
                for (int j = 0; j < 4; j++) mma16(acc[nb * 4 + j], Ah, b0h[j], b1h[j]);
                #pragma unroll
                for (int j = 0; j < 4; j++) mma16(acc[nb * 4 + j], Ah, b0l[j], b1l[j]);
                #pragma unroll
                for (int j = 0; j < 4; j++) mma16(acc[nb * 4 + j], Al, b0h[j], b1h[j]);
            }
        }
        __syncthreads();
    }

    if (which == 2) {
        // V: fp16 pairs along n straight from adjacent accumulator cols
        #pragma unroll
        for (int na = 0; na < 16; na++) {
            int colE = n0 + na * 8 + 2 * tig;
            int ch0 = or0 + iw + g;
            float bb0 = bv[ch0], bb8 = bv[ch0 + 8];
            size_t i0v = ((size_t)(b * 4 + (ch0 >> 6)) * 64 + (ch0 & 63)) * 512 + (colE >> 1);
            g_Vp[i0v] = packhf(acc[na][0] + bb0, acc[na][1] + bb0);
            int ch1 = ch0 + 8;
            size_t i1v = ((size_t)(b * 4 + (ch1 >> 6)) * 64 + (ch1 & 63)) * 512 + (colE >> 1);
            g_Vp[i1v] = packhf(acc[na][2] + bb8, acc[na][3] + bb8);
        }
    } else {
        // Q/K: transpose through smem, pack to g_PK [bh][n][k2]
        const float* bias = (which == 0) ? bq : bk;
        float* Of = (float*)sm;               // [128][132]
        #pragma unroll
        for (int na = 0; na < 16; na++) {
            int row0 = iw + g, col = na * 8 + 2 * tig;
            float bb0 = bias[or0 + row0], bb8 = bias[or0 + row0 + 8];
            Of[row0 * 132 + col]           = acc[na][0] + bb0;
            Of[row0 * 132 + col + 1]       = acc[na][1] + bb0;
            Of[(row0 + 8) * 132 + col]     = acc[na][2] + bb8;
            Of[(row0 + 8) * 132 + col + 1] = acc[na][3] + bb8;
        }
        __syncthreads();
        const int k2off = (which == 0) ? 32 : 0;
        #pragma unroll
        for (int it = 0; it < 32; it++) {
            int c = tid + it * 256;
            int k2l = c & 63, n = c >> 6;     // n 0..127
            float e = Of[(2 * k2l) * 132 + n];
            float o = Of[(2 * k2l + 1) * 132 + n];
            uint32_t h, l;
            split2(e, o, h, l);
            int ch = or0 + 2 * k2l;
            size_t idx = ((size_t)(b * 4 + (ch >> 6)) * 1024 + n0 + n) * 64
                         + k2off + ((ch & 63) >> 1);
            g_PKh[idx] = h; g_PKl[idx] = l;
        }
    }
}

// ---------------------------------------------------------------------------
// Kernel 3: fused flash attention. S: 3-pass bf16; PV: single-pass fp16.
// smem (u32): A hi [128][68] @0, A lo @8704; B bufs @17408 (buf 8704 = hi+lo);
//             V bufs @34816 (buf 2304, fp16). Total 39424 u32 = 157696 B.
// ---------------------------------------------------------------------------
constexpr int OFF_AL = 8704;
constexpr int OFF_B  = 17408;
constexpr int BUFB   = 8704;
constexpr int OFF_V  = 34816;
constexpr int BUFV   = 2304;
constexpr int SM_U32 = 39424;

__global__ void __launch_bounds__(256, 1)
attn_fused(float* __restrict__ out) {
    extern __shared__ uint32_t sm[];
    const int bh = blockIdx.y, h = bh & 3;
    const int i0 = blockIdx.x * 128;
    const int tid = threadIdx.x, lane = tid & 31, warp = tid >> 5;
    const int g = lane >> 2, tig = lane & 3;
    const int iw = warp * 16;
    const int quad = lane >> 3, tq = lane & 7;

    const int abase = (iw + (quad & 1) * 8 + tq) * 68 + (quad >> 1) * 4;
    const int brow  = (quad >> 1) * 8 + tq;
    const int bhalf = (quad & 1) * 4;
    const int vbase = ((quad & 1) * 8 + tq) * 36 + (quad >> 1) * 4;

    #pragma unroll
    for (int it = 0; it < 16; it++) {
        int c = tid + it * 256;
        int hl = c >> 11, r = (c >> 4) & 127, ch = c & 15;
        const uint32_t* src = (ch < 8)
            ? (hl ? g_PKl : g_PKh) + ((size_t)bh * 1024 + i0 + r) * 64 + 32 + ch * 4
            : (hl ? g_Rpl : g_Rph) + ((size_t)h * 1024 + i0 + r) * 32 + (ch - 8) * 4;
        cp16(sptr(sm + (hl ? OFF_AL : 0) + r * 68 + ch * 4), src);
    }
    auto stageBV = [&](int jt, int buf) {
        #pragma unroll
        for (int it = 0; it < 8; it++) {              // B: 2048 chunks
            int c = tid + it * 256;
            int hl = c >> 10, r = (c >> 4) & 63, ch = c & 15;
            const uint32_t* src = (hl ? g_PKl : g_PKh) +
                ((size_t)bh * 1024 + jt * 64 + r) * 64 + ch * 4;
            cp16(sptr(sm + OFF_B + buf * BUFB + hl * 4352 + r * 68 + ch * 4), src);
        }
        #pragma unroll
        for (int it = 0; it < 2; it++) {              // V: 512 chunks (fp16)
            int c = tid + it * 256;
            int r = (c >> 3) & 63, ch = c & 7;
            const uint32_t* src = g_Vp + ((size_t)bh * 64 + r) * 512 + jt * 32 + ch * 4;
            cp16(sptr(sm + OFF_V + buf * BUFV + r * 36 + ch * 4), src);
        }
    };
    stageBV(0, 0);
    cpcommit();

    float m0 = -1e30f, m1 = -1e30f, s0 = 0.f, s1 = 0.f;
    float Oa[4][2][4] = {};

    for (int jt = 0; jt < 16; jt++) {
        cpwait0();
        __syncthreads();
        if (jt < 15) { stageBV(jt + 1, (jt + 1) & 1); cpcommit(); }
        const int bb = OFF_B + (jt & 1) * BUFB;
        const int vb = OFF_V + (jt & 1) * BUFV;

        // ---- S = [Q;R]^T [K;Q] over k=128 (3-pass bf16) ----
        float sacc[8][4] = {};
        #pragma unroll
        for (int kc = 0; kc < 8; kc++) {
            uint32_t Ah[4], Al[4];
            ldm4(Ah, sptr(sm + abase + kc * 8));
            ldm4(Al, sptr(sm + OFF_AL + abase + kc * 8));
            uint32_t Bh4[4][4], Bl4[4][4];
            #pragma unroll
            for (int na2 = 0; na2 < 4; na2++) {
                int bi = bb + (na2 * 16 + brow) * 68 + kc * 8 + bhalf;
                ldm4(Bh4[na2], sptr(sm + bi));
                ldm4(Bl4[na2], sptr(sm + bi + 4352));
            }
            #pragma unroll
            for (int na2 = 0; na2 < 4; na2++) {
                mma16(sacc[2 * na2],     Ah, Bh4[na2][0], Bh4[na2][1]);
                mma16(sacc[2 * na2 + 1], Ah, Bh4[na2][2], Bh4[na2][3]);
            }
            #pragma unroll
            for (int na2 = 0; na2 < 4; na2++) {
                mma16(sacc[2 * na2],     Ah, Bl4[na2][0], Bl4[na2][1]);
                mma16(sacc[2 * na2 + 1], Ah, Bl4[na2][2], Bl4[na2][3]);
            }
            #pragma unroll
            for (int na2 = 0; na2 < 4; na2++) {
                mma16(sacc[2 * na2],     Al, Bh4[na2][0], Bh4[na2][1]);
                mma16(sacc[2 * na2 + 1], Al, Bh4[na2][2], Bh4[na2][3]);
            }
        }

        // ---- online softmax ----
        float tm0 = -1e30f, tm1 = -1e30f;
        #pragma unroll
        for (int na = 0; na < 8; na++) {
            tm0 = fmaxf(tm0, fmaxf(sacc[na][0], sacc[na][1]));
            tm1 = fmaxf(tm1, fmaxf(sacc[na][2], sacc[na][3]));
        }
        tm0 = fmaxf(tm0, __shfl_xor_sync(0xffffffffu, tm0, 1));
        tm0 = fmaxf(tm0, __shfl_xor_sync(0xffffffffu, tm0, 2));
        tm1 = fmaxf(tm1, __shfl_xor_sync(0xffffffffu, tm1, 1));
        tm1 = fmaxf(tm1, __shfl_xor_sync(0xffffffffu, tm1, 2));
        float mn0 = fmaxf(m0, tm0), mn1 = fmaxf(m1, tm1);
        float sc0 = __expf(m0 - mn0), sc1 = __expf(m1 - mn1);
        m0 = mn0; m1 = mn1;

        float ps0 = 0.f, ps1 = 0.f;
        #pragma unroll
        for (int na = 0; na < 8; na++) {
            sacc[na][0] = __expf(sacc[na][0] - m0);
            sacc[na][1] = __expf(sacc[na][1] - m0);
            sacc[na][2] = __expf(sacc[na][2] - m1);
            sacc[na][3] = __expf(sacc[na][3] - m1);
            ps0 += sacc[na][0] + sacc[na][1];
            ps1 += sacc[na][2] + sacc[na][3];
        }
        s0 = s0 * sc0 + ps0;
        s1 = s1 * sc1 + ps1;

        float f0 = __shfl_sync(0xffffffffu, sc0, 8 * tig);
        float f1 = __shfl_sync(0xffffffffu, sc0, 8 * tig + 4);
        float q0 = __shfl_sync(0xffffffffu, sc1, 8 * tig);
        float q1 = __shfl_sync(0xffffffffu, sc1, 8 * tig + 4);
        #pragma unroll
        for (int ma = 0; ma < 4; ma++) {
            Oa[ma][0][0] *= f0; Oa[ma][0][1] *= f1; Oa[ma][0][2] *= f0; Oa[ma][0][3] *= f1;
            Oa[ma][1][0] *= q0; Oa[ma][1][1] *= q1; Oa[ma][1][2] *= q0; Oa[ma][1][3] *= q1;
        }

        // ---- PV: single-pass fp16 (P hi only, V fp16) ----
        #pragma unroll
        for (int kc = 0; kc < 4; kc++) {
            uint32_t p00 = packhf(sacc[2 * kc][0],     sacc[2 * kc][1]);
            uint32_t p01 = packhf(sacc[2 * kc + 1][0], sacc[2 * kc + 1][1]);
            uint32_t p80 = packhf(sacc[2 * kc][2],     sacc[2 * kc][3]);
            uint32_t p81 = packhf(sacc[2 * kc + 1][2], sacc[2 * kc + 1][3]);
            uint32_t Vh4[4][4];
            #pragma unroll
            for (int ma = 0; ma < 4; ma++)
                ldm4(Vh4[ma], sptr(sm + vb + ma * 16 * 36 + vbase + kc * 8));
            #pragma unroll
            for (int ma = 0; ma < 4; ma++) {
                mma16h(Oa[ma][0], Vh4[ma], p00, p01);
                mma16h(Oa[ma][1], Vh4[ma], p80, p81);
            }
        }
    }

    // ---- epilogue ----
    s0 += __shfl_xor_sync(0xffffffffu, s0, 1);
    s0 += __shfl_xor_sync(0xffffffffu, s0, 2);
    s1 += __shfl_xor_sync(0xffffffffu, s1, 1);
    s1 += __shfl_xor_sync(0xffffffffu, s1, 2);
    float i00 = 1.f / __shfl_sync(0xffffffffu, s0, 8 * tig);
    float i01 = 1.f / __shfl_sync(0xffffffffu, s0, 8 * tig + 4);
    float i10 = 1.f / __shfl_sync(0xffffffffu, s1, 8 * tig);
    float i11 = 1.f / __shfl_sync(0xffffffffu, s1, 8 * tig + 4);

    __syncthreads();
    float* Of = (float*)(sm + OFF_B);     // [64 d][132]
    #pragma unroll
    for (int ma = 0; ma < 4; ma++) {
        int d0 = ma * 16 + g;
        #pragma unroll
        for (int ni = 0; ni < 2; ni++) {
            float ie = ni ? i10 : i00, io = ni ? i11 : i01;
            int col = iw + ni * 8 + 2 * tig;
            Of[d0 * 132 + col]           = Oa[ma][ni][0] * ie;
            Of[d0 * 132 + col + 1]       = Oa[ma][ni][1] * io;
            Of[(d0 + 8) * 132 + col]     = Oa[ma][ni][2] * ie;
            Of[(d0 + 8) * 132 + col + 1] = Oa[ma][ni][3] * io;
        }
    }
    __syncthreads();
    #pragma unroll
    for (int it = 0; it < 8; it++) {
        int c = tid + it * 256;
        int row = c >> 5, col4 = c & 31;
        float4 v = *(float4*)(Of + row * 132 + col4 * 4);
        *(float4*)(out + ((size_t)bh * 64 + row) * 1024 + i0 + col4 * 4) = v;
    }
}

// ---------------------------------------------------------------------------
extern "C" void kernel_launch(void* const* d_in, const int* in_sizes, int n_in,
                              void* d_out, int out_size) {
    const float* x    = (const float*)d_in[0];
    const float* Wq   = (const float*)d_in[1];
    const float* bq   = (const float*)d_in[2];
    const float* Wk   = (const float*)d_in[3];
    const float* bk   = (const float*)d_in[4];
    const float* Wv   = (const float*)d_in[5];
    const float* bv   = (const float*)d_in[6];
    const float* relh = (const float*)d_in[7];
    const float* relw = (const float*)d_in[8];
    float* out = (float*)d_out;

    cudaFuncSetAttribute(proj_mma, cudaFuncAttributeMaxDynamicSharedMemorySize,
                         PJ_U32 * 4);
    cudaFuncSetAttribute(attn_fused, cudaFuncAttributeMaxDynamicSharedMemorySize,
                         SM_U32 * 4);

    split_xw<<<2048, 256>>>(x, Wq, Wk, Wv);
    pack_rel<<<128, 256>>>(relh, relw);
    proj_mma<<<dim3(Nv / 128, 6, Bv), 256, PJ_U32 * 4>>>(bq, bk, bv);
    attn_fused<<<dim3(8, 64), 256, SM_U32 * 4>>>(out);
}

// round 17
// speedup vs baseline: 4.0608x; 1.0141x over previous
#include <cuda_runtime.h>
#include <cuda_bf16.h>
#include <stdint.h>

constexpr int Bv = 16, Hv = 4, Dv = 64, Cv = 256, Nv = 1024;

// ---------------- static device scratch ------------------------------------
// g_PK: [bh][n][k2 0..63]  (k2 0..31 = K pairs along d, 32..63 = Q pairs)
__device__ uint32_t g_PKh[64 * 1024 * 64], g_PKl[64 * 1024 * 64];
__device__ uint32_t g_Vp[64 * 64 * 512];                            // [bh][d][n2] fp16x2
__device__ uint32_t g_Rph[4 * 1024 * 32],  g_Rpl[4 * 1024 * 32];    // [h][n][k2]
__device__ uint32_t g_xPh[16 * 128 * 1024], g_xPl[16 * 128 * 1024]; // [b][k2][n]
__device__ uint32_t g_WPh[128 * 768], g_WPl[128 * 768];             // [k2][o]

// ---------------- helpers ---------------------------------------------------
__device__ __forceinline__ uint32_t sptr(const void* p) {
    return (uint32_t)__cvta_generic_to_shared(p);
}
__device__ __forceinline__ void cp16(uint32_t d, const void* s) {
    asm volatile("cp.async.cg.shared.global [%0],[%1],16;\n" :: "r"(d), "l"(s));
}
__device__ __forceinline__ void cpcommit() { asm volatile("cp.async.commit_group;\n"); }
__device__ __forceinline__ void cpwait0()  { asm volatile("cp.async.wait_group 0;\n" ::: "memory"); }
__device__ __forceinline__ void cpwait1()  { asm volatile("cp.async.wait_group 1;\n" ::: "memory"); }
__device__ __forceinline__ void ldm4(uint32_t* r, uint32_t a) {
    asm volatile("ldmatrix.sync.aligned.m8n8.x4.shared.b16 {%0,%1,%2,%3},[%4];\n"
                 : "=r"(r[0]), "=r"(r[1]), "=r"(r[2]), "=r"(r[3]) : "r"(a));
}
__device__ __forceinline__ uint32_t packbf(float e, float o) {
    uint32_t r;
    asm("cvt.rn.bf16x2.f32 %0, %1, %2;" : "=r"(r) : "f"(o), "f"(e));
    return r;
}
__device__ __forceinline__ uint32_t packhf(float e, float o) {   // fp16x2, even in LOW
    uint32_t r;
    asm("cvt.rn.f16x2.f32 %0, %1, %2;" : "=r"(r) : "f"(o), "f"(e));
    return r;
}
__device__ __forceinline__ void split2(float e, float o, uint32_t& h, uint32_t& l) {
    h = packbf(e, o);
    __nv_bfloat162 hb = *reinterpret_cast<__nv_bfloat162*>(&h);
    l = packbf(e - __bfloat162float(hb.x), o - __bfloat162float(hb.y));
}
__device__ __forceinline__ void mma16(float* c, const uint32_t* a, uint32_t b0, uint32_t b1) {
    asm volatile(
        "mma.sync.aligned.m16n8k16.row.col.f32.bf16.bf16.f32 "
        "{%0,%1,%2,%3},{%4,%5,%6,%7},{%8,%9},{%0,%1,%2,%3};\n"
        : "+f"(c[0]), "+f"(c[1]), "+f"(c[2]), "+f"(c[3])
        : "r"(a[0]), "r"(a[1]), "r"(a[2]), "r"(a[3]), "r"(b0), "r"(b1));
}
__device__ __forceinline__ void mma16h(float* c, const uint32_t* a, uint32_t b0, uint32_t b1) {
    asm volatile(
        "mma.sync.aligned.m16n8k16.row.col.f32.f16.f16.f32 "
        "{%0,%1,%2,%3},{%4,%5,%6,%7},{%8,%9},{%0,%1,%2,%3};\n"
        : "+f"(c[0]), "+f"(c[1]), "+f"(c[2]), "+f"(c[3])
        : "r"(a[0]), "r"(a[1]), "r"(a[2]), "r"(a[3]), "r"(b0), "r"(b1));
}

// ---------------------------------------------------------------------------
// Kernel 0: split x and Wcat into bf16 hi/lo pair arrays.
// ---------------------------------------------------------------------------
__global__ void split_xw(const float* __restrict__ x,
                         const float* __restrict__ Wq, const float* __restrict__ Wk,
                         const float* __restrict__ Wv) {
    const int t0 = blockIdx.x * blockDim.x + threadIdx.x;
    const int stride = gridDim.x * blockDim.x;
    for (int i = t0; i < 16 * 128 * 1024; i += stride) {
        int n = i & 1023, k2 = (i >> 10) & 127, b = i >> 17;
        const float* s = x + ((size_t)b * 256 + 2 * k2) * 1024 + n;
        uint32_t h, l;
        split2(s[0], s[1024], h, l);
        g_xPh[i] = h; g_xPl[i] = l;
    }
    for (int i = t0; i < 128 * 768; i += stride) {
        int o = i % 768, k2 = i / 768;
        int which = o >> 8, row = o & 255;
        const float* W = (which == 0) ? Wq : (which == 1) ? Wk : Wv;
        uint32_t h, l;
        split2(W[row * 256 + 2 * k2], W[row * 256 + 2 * k2 + 1], h, l);
        g_WPh[i] = h; g_WPl[i] = l;
    }
}

// ---------------------------------------------------------------------------
// Kernel 1: pack R = rel_h + rel_w, layout [h][n][k2].
// ---------------------------------------------------------------------------
__global__ void pack_rel(const float* __restrict__ relh, const float* __restrict__ relw) {
    const int t0 = blockIdx.x * blockDim.x + threadIdx.x;
    const int stride = gridDim.x * blockDim.x;
    for (int i = t0; i < 4 * 1024 * 32; i += stride) {
        int k2 = i & 31, n = (i >> 5) & 1023, hh = i >> 15;
        int d = 2 * k2;
        float e = relh[(hh * 64 + d) * 32 + (n & 31)]     + relw[(hh * 64 + d) * 32 + (n >> 5)];
        float o = relh[(hh * 64 + d + 1) * 32 + (n & 31)] + relw[(hh * 64 + d + 1) * 32 + (n >> 5)];
        uint32_t h, l;
        split2(e, o, h, l);
        g_Rph[i] = h; g_Rpl[i] = l;
    }
}

// ---------------------------------------------------------------------------
// Kernel 2: QKV projection via bf16 3-pass mma, packing epilogue.
// ---------------------------------------------------------------------------
constexpr int PJ_BUF = 17408;
constexpr int PJ_U32 = 2 * PJ_BUF;

__global__ void __launch_bounds__(256, 1)
proj_mma(const float* __restrict__ bq, const float* __restrict__ bk,
         const float* __restrict__ bv) {
    extern __shared__ uint32_t sm[];
    const int b  = blockIdx.z;
    const int o0 = blockIdx.y * 128;
    const int n0 = blockIdx.x * 128;
    const int tid = threadIdx.x, lane = tid & 31, warp = tid >> 5;
    const int g = lane >> 2, tig = lane & 3;
    const int iw = warp * 16;
    const int which = o0 >> 8;
    const int or0 = o0 & 255;

    auto stage = [&](int s, int buf) {
        int base = buf * PJ_BUF;
        #pragma unroll
        for (int it = 0; it < 8; it++) {
            int c = tid + it * 256;
            int hl = c >> 10, r = (c >> 5) & 31, ch = c & 31;
            const uint32_t* src = (hl ? g_WPl : g_WPh) + (s * 32 + r) * 768 + o0 + ch * 4;
            cp16(sptr(sm + base + hl * 4352 + r * 136 + ch * 4), src);
        }
        #pragma unroll
        for (int it = 0; it < 8; it++) {
            int c = tid + it * 256;
            int hl = c >> 10, r = (c >> 5) & 31, ch = c & 31;
            const uint32_t* src = (hl ? g_xPl : g_xPh) +
                ((size_t)(b * 128 + s * 32 + r)) * 1024 + n0 + ch * 4;
            cp16(sptr(sm + base + 8704 + hl * 4352 + r * 136 + ch * 4), src);
        }
    };
    stage(0, 0);
    cpcommit();

    float acc[16][4] = {};
    for (int s = 0; s < 4; s++) {
        cpwait0();
        __syncthreads();
        if (s < 3) { stage(s + 1, (s + 1) & 1); cpcommit(); }
        const int W0 = (s & 1) * PJ_BUF;
        const int X0 = W0 + 8704;
        #pragma unroll
        for (int kc = 0; kc < 4; kc++) {
            uint32_t Ah[4], Al[4];
            int ab = W0 + (kc * 8 + tig) * 136 + iw + g;
            Ah[0] = sm[ab];           Ah[1] = sm[ab + 8];
            Ah[2] = sm[ab + 4 * 136]; Ah[3] = sm[ab + 4 * 136 + 8];
            Al[0] = sm[ab + 4352];           Al[1] = sm[ab + 4352 + 8];
            Al[2] = sm[ab + 4352 + 4 * 136]; Al[3] = sm[ab + 4352 + 4 * 136 + 8];
            #pragma unroll
            for (int nb = 0; nb < 4; nb++) {
                uint32_t b0h[4], b1h[4], b0l[4], b1l[4];
                #pragma unroll
                for (int j = 0; j < 4; j++) {
                    int bx = X0 + (kc * 8 + tig) * 136 + (nb * 4 + j) * 8 + g;
                    b0h[j] = sm[bx];        b1h[j] = sm[bx + 4 * 136];
                    b0l[j] = sm[bx + 4352]; b1l[j] = sm[bx + 4352 + 4 * 136];
                }
                #pragma unroll
                for (int j = 0; j < 4; j++) mma16(acc[nb * 4 + j], Ah, b0h[j], b1h[j]);
                #pragma unroll
                for (int j = 0; j < 4; j++) mma16(acc[nb * 4 + j], Ah, b0l[j], b1l[j]);
                #pragma unroll
                for (int j = 0; j < 4; j++) mma16(acc[nb * 4 + j], Al, b0h[j], b1h[j]);
            }
        }
        __syncthreads();
    }

    if (which == 2) {
        // V: fp16 pairs along n straight from adjacent accumulator cols
        #pragma unroll
        for (int na = 0; na < 16; na++) {
            int colE = n0 + na * 8 + 2 * tig;
            int ch0 = or0 + iw + g;
            float bb0 = bv[ch0], bb8 = bv[ch0 + 8];
            size_t i0v = ((size_t)(b * 4 + (ch0 >> 6)) * 64 + (ch0 & 63)) * 512 + (colE >> 1);
            g_Vp[i0v] = packhf(acc[na][0] + bb0, acc[na][1] + bb0);
            int ch1 = ch0 + 8;
            size_t i1v = ((size_t)(b * 4 + (ch1 >> 6)) * 64 + (ch1 & 63)) * 512 + (colE >> 1);
            g_Vp[i1v] = packhf(acc[na][2] + bb8, acc[na][3] + bb8);
        }
    } else {
        // Q/K: transpose through smem, pack to g_PK [bh][n][k2]
        const float* bias = (which == 0) ? bq : bk;
        float* Of = (float*)sm;               // [128][132]
        #pragma unroll
        for (int na = 0; na < 16; na++) {
            int row0 = iw + g, col = na * 8 + 2 * tig;
            float bb0 = bias[or0 + row0], bb8 = bias[or0 + row0 + 8];
            Of[row0 * 132 + col]           = acc[na][0] + bb0;
            Of[row0 * 132 + col + 1]       = acc[na][1] + bb0;
            Of[(row0 + 8) * 132 + col]     = acc[na][2] + bb8;
            Of[(row0 + 8) * 132 + col + 1] = acc[na][3] + bb8;
        }
        __syncthreads();
        const int k2off = (which == 0) ? 32 : 0;
        #pragma unroll
        for (int it = 0; it < 32; it++) {
            int c = tid + it * 256;
            int k2l = c & 63, n = c >> 6;     // n 0..127
            float e = Of[(2 * k2l) * 132 + n];
            float o = Of[(2 * k2l + 1) * 132 + n];
            uint32_t h, l;
            split2(e, o, h, l);
            int ch = or0 + 2 * k2l;
            size_t idx = ((size_t)(b * 4 + (ch >> 6)) * 1024 + n0 + n) * 64
                         + k2off + ((ch & 63) >> 1);
            g_PKh[idx] = h; g_PKl[idx] = l;
        }
    }
}

// ---------------------------------------------------------------------------
// Kernel 3: fused flash attention, software-pipelined:
//   S(jt+1) mma interleaved with softmax(jt) scalars; 3-stage cp.async ring.
// smem (u32): A hi @0, A lo @8704; B ring @17408 (3 x 8704); V ring @43520 (3 x 2304).
// Total 50432 u32 = 201728 B.
// ---------------------------------------------------------------------------
constexpr int OFF_AL = 8704;
constexpr int OFF_B  = 17408;
constexpr int BUFB   = 8704;
constexpr int OFF_V  = 43520;
constexpr int BUFV   = 2304;
constexpr int SM_U32 = 50432;

__global__ void __launch_bounds__(256, 1)
attn_fused(float* __restrict__ out) {
    extern __shared__ uint32_t sm[];
    const int bh = blockIdx.y, h = bh & 3;
    const int i0 = blockIdx.x * 128;
    const int tid = threadIdx.x, lane = tid & 31, warp = tid >> 5;
    const int g = lane >> 2, tig = lane & 3;
    const int iw = warp * 16;
    const int quad = lane >> 3, tq = lane & 7;

    const int abase = (iw + (quad & 1) * 8 + tq) * 68 + (quad >> 1) * 4;
    const int brow  = (quad >> 1) * 8 + tq;
    const int bhalf = (quad & 1) * 4;
    const int vbase = ((quad & 1) * 8 + tq) * 36 + (quad >> 1) * 4;

    // ---- stage resident A = [Q;R] hi/lo ----
    #pragma unroll
    for (int it = 0; it < 16; it++) {
        int c = tid + it * 256;
        int hl = c >> 11, r = (c >> 4) & 127, ch = c & 15;
        const uint32_t* src = (ch < 8)
            ? (hl ? g_PKl : g_PKh) + ((size_t)bh * 1024 + i0 + r) * 64 + 32 + ch * 4
            : (hl ? g_Rpl : g_Rph) + ((size_t)h * 1024 + i0 + r) * 32 + (ch - 8) * 4;
        cp16(sptr(sm + (hl ? OFF_AL : 0) + r * 68 + ch * 4), src);
    }
    auto stageBV = [&](int jt, int buf) {
        #pragma unroll
        for (int it = 0; it < 8; it++) {              // B: 2048 chunks
            int c = tid + it * 256;
            int hl = c >> 10, r = (c >> 4) & 63, ch = c & 15;
            const uint32_t* src = (hl ? g_PKl : g_PKh) +
                ((size_t)bh * 1024 + jt * 64 + r) * 64 + ch * 4;
            cp16(sptr(sm + OFF_B + buf * BUFB + hl * 4352 + r * 68 + ch * 4), src);
        }
        #pragma unroll
        for (int it = 0; it < 2; it++) {              // V: 512 chunks (fp16)
            int c = tid + it * 256;
            int r = (c >> 3) & 63, ch = c & 7;
            const uint32_t* src = g_Vp + ((size_t)bh * 64 + r) * 512 + jt * 32 + ch * 4;
            cp16(sptr(sm + OFF_V + buf * BUFV + r * 36 + ch * 4), src);
        }
    };

    float m0 = -1e30f, m1 = -1e30f, s0 = 0.f, s1 = 0.f;
    float Oa[4][2][4] = {};
    float saccA[8][4], saccB[8][4];

    // ---- S block: compute S(tile at B ring-buf bb) into sacc ----
    auto s_blk = [&](float (&sacc)[8][4], int bufn) {
        const int bb = OFF_B + bufn * BUFB;
        #pragma unroll
        for (int na = 0; na < 8; na++)
            #pragma unroll
            for (int c4 = 0; c4 < 4; c4++) sacc[na][c4] = 0.f;
        #pragma unroll
        for (int kc = 0; kc < 8; kc++) {
            uint32_t Ah[4], Al[4];
            ldm4(Ah, sptr(sm + abase + kc * 8));
            ldm4(Al, sptr(sm + OFF_AL + abase + kc * 8));
            uint32_t Bh4[4][4], Bl4[4][4];
            #pragma unroll
            for (int na2 = 0; na2 < 4; na2++) {
                int bi = bb + (na2 * 16 + brow) * 68 + kc * 8 + bhalf;
                ldm4(Bh4[na2], sptr(sm + bi));
                ldm4(Bl4[na2], sptr(sm + bi + 4352));
            }
            #pragma unroll
            for (int na2 = 0; na2 < 4; na2++) {
                mma16(sacc[2 * na2],     Ah, Bh4[na2][0], Bh4[na2][1]);
                mma16(sacc[2 * na2 + 1], Ah, Bh4[na2][2], Bh4[na2][3]);
            }
            #pragma unroll
            for (int na2 = 0; na2 < 4; na2++) {
                mma16(sacc[2 * na2],     Ah, Bl4[na2][0], Bl4[na2][1]);
                mma16(sacc[2 * na2 + 1], Ah, Bl4[na2][2], Bl4[na2][3]);
            }
            #pragma unroll
            for (int na2 = 0; na2 < 4; na2++) {
                mma16(sacc[2 * na2],     Al, Bh4[na2][0], Bh4[na2][1]);
                mma16(sacc[2 * na2 + 1], Al, Bh4[na2][2], Bh4[na2][3]);
            }
        }
    };

    // ---- softmax block (online, updates m/s and rescales Oa) ----
    auto softmax_blk = [&](float (&sacc)[8][4]) {
        float tm0 = -1e30f, tm1 = -1e30f;
        #pragma unroll
        for (int na = 0; na < 8; na++) {
            tm0 = fmaxf(tm0, fmaxf(sacc[na][0], sacc[na][1]));
            tm1 = fmaxf(tm1, fmaxf(sacc[na][2], sacc[na][3]));
        }
        tm0 = fmaxf(tm0, __shfl_xor_sync(0xffffffffu, tm0, 1));
        tm0 = fmaxf(tm0, __shfl_xor_sync(0xffffffffu, tm0, 2));
        tm1 = fmaxf(tm1, __shfl_xor_sync(0xffffffffu, tm1, 1));
        tm1 = fmaxf(tm1, __shfl_xor_sync(0xffffffffu, tm1, 2));
        float mn0 = fmaxf(m0, tm0), mn1 = fmaxf(m1, tm1);
        float sc0 = __expf(m0 - mn0), sc1 = __expf(m1 - mn1);
        m0 = mn0; m1 = mn1;

        float ps0 = 0.f, ps1 = 0.f;
        #pragma unroll
        for (int na = 0; na < 8; na++) {
            sacc[na][0] = __expf(sacc[na][0] - m0);
            sacc[na][1] = __expf(sacc[na][1] - m0);
            sacc[na][2] = __expf(sacc[na][2] - m1);
            sacc[na][3] = __expf(sacc[na][3] - m1);
            ps0 += sacc[na][0] + sacc[na][1];
            ps1 += sacc[na][2] + sacc[na][3];
        }
        s0 = s0 * sc0 + ps0;
        s1 = s1 * sc1 + ps1;

        float f0 = __shfl_sync(0xffffffffu, sc0, 8 * tig);
        float f1 = __shfl_sync(0xffffffffu, sc0, 8 * tig + 4);
        float q0 = __shfl_sync(0xffffffffu, sc1, 8 * tig);
        float q1 = __shfl_sync(0xffffffffu, sc1, 8 * tig + 4);
        #pragma unroll
        for (int ma = 0; ma < 4; ma++) {
            Oa[ma][0][0] *= f0; Oa[ma][0][1] *= f1; Oa[ma][0][2] *= f0; Oa[ma][0][3] *= f1;
            Oa[ma][1][0] *= q0; Oa[ma][1][1] *= q1; Oa[ma][1][2] *= q0; Oa[ma][1][3] *= q1;
        }
    };

    // ---- PV block: single-pass fp16 ----
    auto pv_blk = [&](float (&sacc)[8][4], int bufv) {
        const int vb = OFF_V + bufv * BUFV;
        #pragma unroll
        for (int kc = 0; kc < 4; kc++) {
            uint32_t p00 = packhf(sacc[2 * kc][0],     sacc[2 * kc][1]);
            uint32_t p01 = packhf(sacc[2 * kc + 1][0], sacc[2 * kc + 1][1]);
            uint32_t p80 = packhf(sacc[2 * kc][2],     sacc[2 * kc][3]);
            uint32_t p81 = packhf(sacc[2 * kc + 1][2], sacc[2 * kc + 1][3]);
            uint32_t Vh4[4][4];
            #pragma unroll
            for (int ma = 0; ma < 4; ma++)
                ldm4(Vh4[ma], sptr(sm + vb + ma * 16 * 36 + vbase + kc * 8));
            #pragma unroll
            for (int ma = 0; ma < 4; ma++) {
                mma16h(Oa[ma][0], Vh4[ma], p00, p01);
                mma16h(Oa[ma][1], Vh4[ma], p80, p81);
            }
        }
    };

    // ---- pipelined body: softmax(jt | cur) overlapped with S(jt+1 -> nxt) ----
    auto body = [&](float (&cur)[8][4], float (&nxt)[8][4], int jt) {
        __syncthreads();                              // PV(jt-1) readers done
        if (jt <= 13) { stageBV(jt + 2, (jt + 2) % 3); cpcommit(); cpwait1(); }
        else          { cpwait0(); }
        __syncthreads();                              // buf jt+1 visible
        s_blk(nxt, (jt + 1) % 3);                     // tensor work ...
        softmax_blk(cur);                             // ... interleaved with scalars
        pv_blk(cur, jt % 3);
    };

    // ---- prologue: stage 0 (with A) and 1, compute S(0) ----
    stageBV(0, 0);
    cpcommit();                                        // group0 = A + B/V tile 0
    stageBV(1, 1);
    cpcommit();                                        // group1 = tile 1
    cpwait1();
    __syncthreads();
    s_blk(saccA, 0);

    for (int jt = 0; jt < 14; jt += 2) {
        body(saccA, saccB, jt);
        body(saccB, saccA, jt + 1);
    }
    body(saccA, saccB, 14);
    // final tile 15 (cur = saccB, V buf 15%3 = 0)
    softmax_blk(saccB);
    pv_blk(saccB, 0);

    // ---- epilogue: normalize, transpose through smem, coalesced store ----
    s0 += __shfl_xor_sync(0xffffffffu, s0, 1);
    s0 += __shfl_xor_sync(0xffffffffu, s0, 2);
    s1 += __shfl_xor_sync(0xffffffffu, s1, 1);
    s1 += __shfl_xor_sync(0xffffffffu, s1, 2);
    float i00 = 1.f / __shfl_sync(0xffffffffu, s0, 8 * tig);
    float i01 = 1.f / __shfl_sync(0xffffffffu, s0, 8 * tig + 4);
    float i10 = 1.f / __shfl_sync(0xffffffffu, s1, 8 * tig);
    float i11 = 1.f / __shfl_sync(0xffffffffu, s1, 8 * tig + 4);

    __syncthreads();
    float* Of = (float*)(sm + OFF_B);     // [64 d][132]
    #pragma unroll
    for (int ma = 0; ma < 4; ma++) {
        int d0 = ma * 16 + g;
        #pragma unroll
        for (int ni = 0; ni < 2; ni++) {
            float ie = ni ? i10 : i00, io = ni ? i11 : i01;
            int col = iw + ni * 8 + 2 * tig;
            Of[d0 * 132 + col]           = Oa[ma][ni][0] * ie;
            Of[d0 * 132 + col + 1]       = Oa[ma][ni][1] * io;
            Of[(d0 + 8) * 132 + col]     = Oa[ma][ni][2] * ie;
            Of[(d0 + 8) * 132 + col + 1] = Oa[ma][ni][3] * io;
        }
    }
    __syncthreads();
    #pragma unroll
    for (int it = 0; it < 8; it++) {
        int c = tid + it * 256;
        int row = c >> 5, col4 = c & 31;
        float4 v = *(float4*)(Of + row * 132 + col4 * 4);
        *(float4*)(out + ((size_t)bh * 64 + row) * 1024 + i0 + col4 * 4) = v;
    }
}

// ---------------------------------------------------------------------------
extern "C" void kernel_launch(void* const* d_in, const int* in_sizes, int n_in,
                              void* d_out, int out_size) {
    const float* x    = (const float*)d_in[0];
    const float* Wq   = (const float*)d_in[1];
    const float* bq   = (const float*)d_in[2];
    const float* Wk   = (const float*)d_in[3];
    const float* bk   = (const float*)d_in[4];
    const float* Wv   = (const float*)d_in[5];
    const float* bv   = (const float*)d_in[6];
    const float* relh = (const float*)d_in[7];
    const float* relw = (const float*)d_in[8];
    float* out = (float*)d_out;

    cudaFuncSetAttribute(proj_mma, cudaFuncAttributeMaxDynamicSharedMemorySize,
                         PJ_U32 * 4);
    cudaFuncSetAttribute(attn_fused, cudaFuncAttributeMaxDynamicSharedMemorySize,
                         SM_U32 * 4);

    split_xw<<<2048, 256>>>(x, Wq, Wk, Wv);
    pack_rel<<<128, 256>>>(relh, relw);
    proj_mma<<<dim3(Nv / 128, 6, Bv), 256, PJ_U32 * 4>>>(bq, bk, bv);
    attn_fused<<<dim3(8, 64), 256, SM_U32 * 4>>>(out);
}